// round 11
// baseline (speedup 1.0000x reference)
#include <cuda_runtime.h>
#include <cuda_fp16.h>
#include <cstdint>

// ---------------- problem constants ----------------
// B=64 N=16 C=16 T=256 DH=128 DT=8 DP=128 TOUT=32 P=4 DIN=136

// ---------------- scratch (static device arrays; no allocation) ----------------
__device__ __half g_Hc [64u*16u*256u*144u];  // [row][144] fp16, cols 136..143 = 0
__device__ __half g_P  [64u*16u*256u*256u];  // [row][0:128]=Hc*Wn^T, [128:256]=Hc*Wself^T
__device__ __half g_Z  [64u*16u*256u*128u];  // [row][128] fp16
__device__ __half g_K [1024u*256u*128u];     // [m][t][d]  fp16
__device__ __half g_V [1024u*256u*128u];     // [m][t][d]  fp16
__device__ float g_WhhT [16*128*384];        // [n][k][g]
__device__ __half g_WcatH[256*144];          // rows 0..127 = Wn/sigma, 128..255 = W_self
__device__ __half g_WkvH [256*128];          // rows 0..127 = Wk, 128..255 = Wv
__device__ float g_cWihT[144*384];           // [k][g]
__device__ float g_cWhhT[128*384];           // [k][g]
__device__ float g_Aph  [4*16*16];
__device__ float g_utab [256*8];
__device__ float g_h   [1024*128];
__device__ float g_yA  [1024*16];
__device__ float g_yB  [1024*16];
__device__ float g_ctx [1024*128];
__device__ float g_ymix[1024*16];
__device__ float g_scale[1];

__device__ __forceinline__ float sigm(float x){ return 1.0f/(1.0f+expf(-x)); }

__device__ __forceinline__ void mma16816(float* c, const uint32_t* a, const uint32_t* b) {
    asm volatile("mma.sync.aligned.m16n8k16.row.col.f32.f16.f16.f32 "
        "{%0,%1,%2,%3}, {%4,%5,%6,%7}, {%8,%9}, {%0,%1,%2,%3};"
        : "+f"(c[0]), "+f"(c[1]), "+f"(c[2]), "+f"(c[3])
        : "r"(a[0]), "r"(a[1]), "r"(a[2]), "r"(a[3]), "r"(b[0]), "r"(b[1]));
}

// packed fp32x2 helpers
__device__ __forceinline__ unsigned long long pack2(float x) {
    unsigned long long r;
    asm("mov.b64 %0, {%1, %1};" : "=l"(r) : "f"(x));
    return r;
}
__device__ __forceinline__ void fma2(unsigned long long& acc, unsigned long long a, unsigned long long b) {
    asm("fma.rn.f32x2 %0, %1, %2, %0;" : "+l"(acc) : "l"(a), "l"(b));
}
__device__ __forceinline__ void lds_v2u64(unsigned addr, unsigned long long& lo, unsigned long long& hi) {
    asm volatile("ld.shared.v2.u64 {%0, %1}, [%2];" : "=l"(lo), "=l"(hi) : "r"(addr));
}
__device__ __forceinline__ void unpack2(unsigned long long p, float& lo, float& hi) {
    asm("mov.b64 {%0, %1}, %2;" : "=f"(lo), "=f"(hi) : "l"(p));
}

// ---------------- K0: spectral norm, phase graphs, u table, weight packs ----------------
__global__ void __launch_bounds__(256) k0_prep(
    const float* __restrict__ Wneigh, const float* __restrict__ Wself,
    const float* __restrict__ Wk, const float* __restrict__ Wv,
    const float* __restrict__ S, const float* __restrict__ G,
    const float* __restrict__ tW, const float* __restrict__ tb,
    const float* __restrict__ ltau)
{
    __shared__ float u[128], v[136], red[256], sig;
    int tid = threadIdx.x;
    if (tid < 128) u[tid] = 1.0f / sqrtf(128.0f);
    __syncthreads();
    for (int it = 0; it < 15; it++) {
        float vv = 0.f;
        if (tid < 136) { float s = 0.f; for (int i = 0; i < 128; i++) s += Wneigh[i*136+tid]*u[i]; vv = s; }
        red[tid] = (tid < 136) ? vv*vv : 0.f; __syncthreads();
        for (int o = 128; o > 0; o >>= 1) { if (tid < o) red[tid] += red[tid+o]; __syncthreads(); }
        float nv = sqrtf(red[0]); __syncthreads();
        if (tid < 136) v[tid] = vv / nv;
        __syncthreads();
        float uu = 0.f;
        if (tid < 128) { float s = 0.f; for (int j = 0; j < 136; j++) s += Wneigh[tid*136+j]*v[j]; uu = s; }
        red[tid] = (tid < 128) ? uu*uu : 0.f; __syncthreads();
        for (int o = 128; o > 0; o >>= 1) { if (tid < o) red[tid] += red[tid+o]; __syncthreads(); }
        float nu = sqrtf(red[0]); __syncthreads();
        if (tid < 128) u[tid] = uu / nu;
        __syncthreads();
    }
    {
        float p = 0.f;
        if (tid < 128) { float s = 0.f; for (int j = 0; j < 136; j++) s += Wneigh[tid*136+j]*v[j]; p = u[tid]*s; }
        red[tid] = p; __syncthreads();
        for (int o = 128; o > 0; o >>= 1) { if (tid < o) red[tid] += red[tid+o]; __syncthreads(); }
        if (tid == 0) sig = red[0];
        __syncthreads();
    }
    float inv = 1.0f / sig;
    for (int i = tid; i < 128*144; i += 256) {
        int r = i / 144, cidx = i % 144;
        float wn_ = (cidx < 136) ? Wneigh[r*136 + cidx]*inv : 0.f;
        float ws_ = (cidx < 136) ? Wself[r*136 + cidx] : 0.f;
        g_WcatH[i] = __float2half(wn_);
        g_WcatH[128*144 + i] = __float2half(ws_);
    }
    for (int i = tid; i < 128*128; i += 256) {
        g_WkvH[i] = __float2half(Wk[i]);
        g_WkvH[16384 + i] = __float2half(Wv[i]);
    }
    for (int i = tid; i < 256*8;   i += 256) { int t = i >> 3, j = i & 7;
        g_utab[i] = tanhf(((float)t * (1.0f/255.0f)) * tW[j] + tb[j]); }
    if (tid == 0) g_scale[0] = expf(ltau[0]);
    if (tid < 4) {
        int p = tid; float gg[16]; float gs = 0.f;
        for (int i = 0; i < 16; i++) { float x = G[p*16+i]; float sp = log1pf(expf(x)) + 1e-6f; gg[i] = sp; gs += sp; }
        float gn = 16.0f / fmaxf(gs, 1e-6f);
        for (int i = 0; i < 16; i++) {
            float den = 0.f;
            for (int j = 0; j < 16; j++) { float sv = (i==j) ? 0.f : S[p*256+i*16+j]; den += fabsf(sv); }
            den = fmaxf(den, 1e-6f);
            float gi = gg[i]*gn;
            for (int j = 0; j < 16; j++) { float sv = (i==j) ? 0.f : S[p*256+i*16+j];
                g_Aph[p*256+i*16+j] = sv/den*gi; }
        }
    }
}

// ---------------- weight transposes ----------------
__global__ void k_trans(const float* __restrict__ Whh,
                        const float* __restrict__ cWih, const float* __restrict__ cWhh)
{
    int i = blockIdx.x*256 + threadIdx.x;
    const int T1 = 16*384*128, T2 = 384*144, T3 = 384*128;
    if (i < T1) {
        int n = i / 49152, r = i % 49152, gg = r / 128, k = r % 128;
        g_WhhT[n*49152 + k*384 + gg] = Whh[i];
    } else if (i < T1 + T2) {
        int j = i - T1; int gg = j / 144, k = j % 144;
        g_cWihT[k*384 + gg] = cWih[j];
    } else if (i < T1 + T2 + T3) {
        int j = i - T1 - T2; int gg = j / 128, k = j % 128;
        g_cWhhT[k*384 + gg] = cWhh[j];
    }
}

// ---------------- K2: GRU scan over T with fused Gx compute + LN, writes Hc (fp16) ----------------
#define K2_SMEM_FLOATS 19776
__global__ void __launch_bounds__(384) k2_gru(const float* __restrict__ X,
                                              const float* __restrict__ Wih,
                                              const float* __restrict__ bih,
                                              const float* __restrict__ bhh,
                                              const float* __restrict__ lng,
                                              const float* __restrict__ lnb)
{
    extern __shared__ float sm[];
    float* h_s   = sm;
    float* sA    = sm + 1024;
    float* sB    = sm + 2048;
    float* sXn   = sm + 3072;
    float* sHn   = sm + 4096;
    float* Wih_s = sm + 5120;
    float* Xs    = sm + 11264;
    float* lg    = sm + 19456;
    float* lb    = sm + 19584;
    float* red1  = sm + 19712;
    float* red2  = sm + 19744;

    int g = threadIdx.x;
    int n = blockIdx.x >> 3, bg = blockIdx.x & 7;
    if (g < 128) { lg[g] = lng[g]; lb[g] = lnb[g]; }
    for (int i = g; i < 1024; i += 384) h_s[i] = 0.f;
    for (int i = g; i < 6144; i += 384) { int g2 = i >> 4, c = i & 15;
        Wih_s[c*384 + g2] = Wih[n*6144 + i]; }
    float bhh_g = bhh[n*384 + g];
    float bih_g = bih[n*384 + g];
    const float* wp = g_WhhT + n*49152 + g;
    unsigned hbase  = (unsigned)__cvta_generic_to_shared(h_s);
    unsigned xbase  = (unsigned)__cvta_generic_to_shared(Xs);
    unsigned long long bih2 = pack2(bih_g);
    __syncthreads();

    for (int t = 0; t < 256; t++) {
        int tc = t & 63;
        if (tc == 0) {
            __syncthreads();
            for (int i = g; i < 8192; i += 384) {
                int b = i >> 10, r = i & 1023, c = r >> 6, tcc = r & 63;
                Xs[c*512 + tcc*8 + b] = X[(size_t)((bg*8 + b)*16 + n)*4096 + c*256 + t + tcc];
            }
            __syncthreads();
        }
        unsigned long long a01 = 0, a23 = 0, a45 = 0, a67 = 0;
        unsigned long long g01 = bih2, g23 = bih2, g45 = bih2, g67 = bih2;
        #pragma unroll
        for (int c = 0; c < 16; c++) {
            unsigned long long w2 = pack2(Wih_s[c*384 + g]);
            unsigned long long x01, x23, x45, x67;
            unsigned xaddr = xbase + (unsigned)(c*512 + tc*8) * 4u;
            lds_v2u64(xaddr, x01, x23);
            lds_v2u64(xaddr + 16u, x45, x67);
            fma2(g01, w2, x01); fma2(g23, w2, x23);
            fma2(g45, w2, x45); fma2(g67, w2, x67);
        }
        #pragma unroll 8
        for (int k = 0; k < 128; k++) {
            unsigned long long w2 = pack2(wp[(size_t)k*384]);
            unsigned long long h01, h23, h45, h67;
            unsigned haddr = hbase + (unsigned)(k*32);
            lds_v2u64(haddr, h01, h23);
            lds_v2u64(haddr + 16u, h45, h67);
            fma2(a01, w2, h01); fma2(a23, w2, h23);
            fma2(a45, w2, h45); fma2(a67, w2, h67);
        }
        float acc[8], gx[8];
        unpack2(a01, acc[0], acc[1]); unpack2(a23, acc[2], acc[3]);
        unpack2(a45, acc[4], acc[5]); unpack2(a67, acc[6], acc[7]);
        unpack2(g01, gx[0], gx[1]);   unpack2(g23, gx[2], gx[3]);
        unpack2(g45, gx[4], gx[5]);   unpack2(g67, gx[6], gx[7]);
        if (g < 128) {
            #pragma unroll
            for (int b = 0; b < 8; b++) sA[g*8 + b] = gx[b] + acc[b] + bhh_g;
        } else if (g < 256) {
            #pragma unroll
            for (int b = 0; b < 8; b++) sB[(g-128)*8 + b] = gx[b] + acc[b] + bhh_g;
        } else {
            #pragma unroll
            for (int b = 0; b < 8; b++) { sXn[(g-256)*8 + b] = gx[b]; sHn[(g-256)*8 + b] = acc[b] + bhh_g; }
        }
        __syncthreads();
        float hnew[8];
        if (g < 128) {
            float s1[8], s2[8];
            #pragma unroll
            for (int b = 0; b < 8; b++) {
                float r  = sigm(sA[g*8 + b]);
                float z  = sigm(sB[g*8 + b]);
                float nn = tanhf(sXn[g*8 + b] + r*sHn[g*8 + b]);
                float hv = (1.f - z)*nn + z*h_s[g*8 + b];
                hnew[b] = hv; h_s[g*8 + b] = hv;
                s1[b] = hv; s2[b] = hv*hv;
            }
            #pragma unroll
            for (int off = 16; off > 0; off >>= 1) {
                #pragma unroll
                for (int b = 0; b < 8; b++) {
                    s1[b] += __shfl_down_sync(0xffffffffu, s1[b], off);
                    s2[b] += __shfl_down_sync(0xffffffffu, s2[b], off);
                }
            }
            if ((g & 31) == 0) { int w = g >> 5;
                #pragma unroll
                for (int b = 0; b < 8; b++) { red1[w*8 + b] = s1[b]; red2[w*8 + b] = s2[b]; }
            }
        }
        __syncthreads();
        if (g < 128) {
            #pragma unroll
            for (int b = 0; b < 8; b++) {
                float mean = (red1[b] + red1[8+b] + red1[16+b] + red1[24+b]) * 0.0078125f;
                float msq  = (red2[b] + red2[8+b] + red2[16+b] + red2[24+b]) * 0.0078125f;
                float var  = msq - mean*mean;
                float rstd = rsqrtf(var + 1e-5f);
                int bm = (bg*8 + b)*16 + n;
                g_Hc[((size_t)bm*256 + t)*144 + g] = __float2half((hnew[b] - mean)*rstd*lg[g] + lb[g]);
            }
        } else if (g < 136) {
            float uv = g_utab[t*8 + (g - 128)];
            #pragma unroll
            for (int b = 0; b < 8; b++) {
                int bm = (bg*8 + b)*16 + n;
                g_Hc[((size_t)bm*256 + t)*144 + g] = __float2half(uv);
            }
        } else if (g < 144) {
            #pragma unroll
            for (int b = 0; b < 8; b++) {
                int bm = (bg*8 + b)*16 + n;
                g_Hc[((size_t)bm*256 + t)*144 + g] = __float2half(0.f);
            }
        }
        __syncthreads();
    }
}

// ---------------- K3: P = Hc @ Wcat^T via HMMA  (262144 x 144) @ (144 x 256) ----------------
__global__ void __launch_bounds__(256) k3_hgemm()
{
    extern __shared__ __half smh[];
    const int PITCH = 168;
    __half* As = smh;
    __half* Bs = smh + 128*PITCH;
    int tid = threadIdx.x;
    size_t row0 = (size_t)blockIdx.x * 128;
    int col0 = blockIdx.y * 128;
    for (int i = tid; i < 128*18; i += 256) {
        int r = i / 18, c = i % 18;
        *(int4*)(As + r*PITCH + c*8) = *(const int4*)(g_Hc + (row0 + r)*144 + c*8);
    }
    for (int i = tid; i < 128*18; i += 256) {
        int r = i / 18, c = i % 18;
        *(int4*)(Bs + r*PITCH + c*8) = *(const int4*)(g_WcatH + (size_t)(col0 + r)*144 + c*8);
    }
    __syncthreads();
    int w = tid >> 5, l = tid & 31;
    int wm = w & 1, wn = w >> 1;
    int lr = l >> 2, lk = (l & 3)*2;
    float c[4][4][4];
    #pragma unroll
    for (int mi = 0; mi < 4; mi++)
        #pragma unroll
        for (int ni = 0; ni < 4; ni++)
            #pragma unroll
            for (int q = 0; q < 4; q++) c[mi][ni][q] = 0.f;
    #pragma unroll
    for (int kc = 0; kc < 9; kc++) {
        int k0 = kc*16;
        uint32_t a[4][4], b[4][2];
        #pragma unroll
        for (int mi = 0; mi < 4; mi++) {
            const __half* ap = As + (wm*64 + mi*16 + lr)*PITCH + k0 + lk;
            a[mi][0] = *(const uint32_t*)(ap);
            a[mi][1] = *(const uint32_t*)(ap + 8*PITCH);
            a[mi][2] = *(const uint32_t*)(ap + 8);
            a[mi][3] = *(const uint32_t*)(ap + 8*PITCH + 8);
        }
        #pragma unroll
        for (int ni = 0; ni < 4; ni++) {
            const __half* bp = Bs + (wn*32 + ni*8 + lr)*PITCH + k0 + lk;
            b[ni][0] = *(const uint32_t*)(bp);
            b[ni][1] = *(const uint32_t*)(bp + 8);
        }
        #pragma unroll
        for (int mi = 0; mi < 4; mi++)
            #pragma unroll
            for (int ni = 0; ni < 4; ni++)
                mma16816(c[mi][ni], a[mi], b[ni]);
    }
    #pragma unroll
    for (int mi = 0; mi < 4; mi++) {
        size_t ra = row0 + wm*64 + mi*16 + lr;
        #pragma unroll
        for (int ni = 0; ni < 4; ni++) {
            int cc = col0 + wn*32 + ni*8 + lk;
            *(__half2*)(g_P + ra*256 + cc)     = __floats2half2_rn(c[mi][ni][0], c[mi][ni][1]);
            *(__half2*)(g_P + (ra+8)*256 + cc) = __floats2half2_rn(c[mi][ni][2], c[mi][ni][3]);
        }
    }
}

// ---------------- K4: graph mix + self + leaky -> Z (vectorized fp16 IO) ----------------
__global__ void __launch_bounds__(256) k4_mix(const int* __restrict__ phases)
{
    __shared__ float Am[256], sP[2048];
    int tid = threadIdx.x; int b = blockIdx.y; int t0 = blockIdx.x*8;
    Am[tid] = g_Aph[phases[b]*256 + tid];
    int i_row = tid >> 4;        // 0..15 (region i / staging row j)
    int oct   = tid & 15;        // d-octet 0..15 -> d0 = oct*8
    int d0 = oct*8;
    for (int tc = 0; tc < 8; tc++) {
        int t = t0 + tc;
        __syncthreads();
        // stage neighbor half: sP[j*128 + d] for 16 j x 128 d (one int4 per thread)
        {
            int4 pk = *(const int4*)(g_P + ((size_t)(b*16 + i_row)*256 + t)*256 + d0);
            const __half2* hh = (const __half2*)&pk;
            #pragma unroll
            for (int q = 0; q < 4; q++) {
                float2 f = __half22float2(hh[q]);
                sP[i_row*128 + d0 + q*2]     = f.x;
                sP[i_row*128 + d0 + q*2 + 1] = f.y;
            }
        }
        __syncthreads();
        // self half + mix + store (one int4 in, one int4 out per thread)
        {
            size_t row = (size_t)(b*16 + i_row)*256 + t;
            int4 ps = *(const int4*)(g_P + row*256 + 128 + d0);
            const __half2* hh = (const __half2*)&ps;
            float accv[8];
            #pragma unroll
            for (int q = 0; q < 4; q++) {
                float2 f = __half22float2(hh[q]);
                accv[q*2] = f.x; accv[q*2+1] = f.y;
            }
            #pragma unroll
            for (int j = 0; j < 16; j++) {
                float aij = Am[i_row*16 + j];
                const float* pj = sP + j*128 + d0;
                #pragma unroll
                for (int q = 0; q < 8; q++) accv[q] = fmaf(aij, pj[q], accv[q]);
            }
            __half2 outh[4];
            #pragma unroll
            for (int q = 0; q < 4; q++) {
                float v0 = accv[q*2],  v1 = accv[q*2+1];
                v0 = (v0 >= 0.f) ? v0 : 0.1f*v0;
                v1 = (v1 >= 0.f) ? v1 : 0.1f*v1;
                outh[q] = __floats2half2_rn(v0, v1);
            }
            *(int4*)(g_Z + row*128 + d0) = *(int4*)outh;
        }
    }
}

// ---------------- K5: K|V = Z @ Wkv^T via HMMA; both stored [m][t][d] fp16 ----------------
__global__ void __launch_bounds__(256) k5_hgemm()
{
    extern __shared__ __half smh[];
    const int PITCH = 136;
    __half* As = smh;
    __half* Bs = smh + 128*PITCH;
    int tid = threadIdx.x;
    size_t row0 = (size_t)blockIdx.x * 128;
    int col0 = blockIdx.y * 128;
    for (int i = tid; i < 128*16; i += 256) {
        int r = i >> 4, c = i & 15;
        *(int4*)(As + r*PITCH + c*8) = *(const int4*)(g_Z + (row0 + r)*128 + c*8);
    }
    for (int i = tid; i < 128*16; i += 256) {
        int r = i >> 4, c = i & 15;
        *(int4*)(Bs + r*PITCH + c*8) = *(const int4*)(g_WkvH + (size_t)(col0 + r)*128 + c*8);
    }
    __syncthreads();
    int w = tid >> 5, l = tid & 31;
    int wm = w & 1, wn = w >> 1;
    int lr = l >> 2, lk = (l & 3)*2;
    float c[4][4][4];
    #pragma unroll
    for (int mi = 0; mi < 4; mi++)
        #pragma unroll
        for (int ni = 0; ni < 4; ni++)
            #pragma unroll
            for (int q = 0; q < 4; q++) c[mi][ni][q] = 0.f;
    #pragma unroll
    for (int kc = 0; kc < 8; kc++) {
        int k0 = kc*16;
        uint32_t a[4][4], b[4][2];
        #pragma unroll
        for (int mi = 0; mi < 4; mi++) {
            const __half* ap = As + (wm*64 + mi*16 + lr)*PITCH + k0 + lk;
            a[mi][0] = *(const uint32_t*)(ap);
            a[mi][1] = *(const uint32_t*)(ap + 8*PITCH);
            a[mi][2] = *(const uint32_t*)(ap + 8);
            a[mi][3] = *(const uint32_t*)(ap + 8*PITCH + 8);
        }
        #pragma unroll
        for (int ni = 0; ni < 4; ni++) {
            const __half* bp = Bs + (wn*32 + ni*8 + lr)*PITCH + k0 + lk;
            b[ni][0] = *(const uint32_t*)(bp);
            b[ni][1] = *(const uint32_t*)(bp + 8);
        }
        #pragma unroll
        for (int mi = 0; mi < 4; mi++)
            #pragma unroll
            for (int ni = 0; ni < 4; ni++)
                mma16816(c[mi][ni], a[mi], b[ni]);
    }
    __half* dst = (blockIdx.y == 0) ? g_K : g_V;
    #pragma unroll
    for (int mi = 0; mi < 4; mi++) {
        size_t ra = row0 + wm*64 + mi*16 + lr;
        size_t rb = ra + 8;
        #pragma unroll
        for (int ni = 0; ni < 4; ni++) {
            int cc = wn*32 + ni*8 + lk;
            *(__half2*)(dst + ra*128 + cc) = __floats2half2_rn(c[mi][ni][0], c[mi][ni][1]);
            *(__half2*)(dst + rb*128 + cc) = __floats2half2_rn(c[mi][ni][2], c[mi][ni][3]);
        }
    }
}

// ---------------- K6: decode init ----------------
__global__ void k6_init()
{
    int i = blockIdx.x*256 + threadIdx.x;
    if (i < 1024*128) { int m = i >> 7, d = i & 127;
        g_h[i] = __half2float(g_Z[((size_t)m*256 + 255)*128 + d]); }
    if (i < 1024*16) { g_yA[i] = 0.f; g_yB[i] = 0.f; }
}

// ---------------- D-S1: y-mix + attention (vectorized) -> g_ctx, g_ymix ----------------
__global__ void __launch_bounds__(256) d_s1(const int* __restrict__ phases, int step)
{
    __shared__ float ys[256], h_s[128], sc[256], arow[16], wred[8], cpart[1024];
    int tid = threadIdx.x; int m = blockIdx.x; int b = m >> 4, n = m & 15;
    const float* y_in = (step & 1) ? g_yB : g_yA;
    ys[tid] = y_in[b*256 + tid];
    if (tid < 16) arow[tid] = g_Aph[phases[b]*256 + n*16 + tid];
    if (tid < 128) h_s[tid] = g_h[m*128 + tid];
    __syncthreads();
    if (tid < 16) {
        float a = 0.f;
        #pragma unroll
        for (int j = 0; j < 16; j++) a = fmaf(arow[j], ys[j*16 + tid], a);
        g_ymix[m*16 + tid] = ys[n*16 + tid] + 0.3f*a;
    }
    // scores: thread = t; K row [t][0..127] via 16 int4 loads
    const int4* kp = (const int4*)(g_K + (size_t)m*32768 + tid*128);
    float s = 0.f;
    #pragma unroll
    for (int i = 0; i < 16; i++) {
        int4 pk = kp[i];
        const __half2* hh = (const __half2*)&pk;
        #pragma unroll
        for (int q = 0; q < 4; q++) {
            float2 f = __half22float2(hh[q]);
            s = fmaf(f.x, h_s[i*8 + q*2], s);
            s = fmaf(f.y, h_s[i*8 + q*2 + 1], s);
        }
    }
    s *= g_scale[0];
    int lane = tid & 31, wid = tid >> 5;
    float wm = s;
    #pragma unroll
    for (int o = 16; o > 0; o >>= 1) wm = fmaxf(wm, __shfl_xor_sync(0xffffffffu, wm, o));
    if (lane == 0) wred[wid] = wm;
    __syncthreads();
    float mx = wred[0];
    #pragma unroll
    for (int w = 1; w < 8; w++) mx = fmaxf(mx, wred[w]);
    float e = expf(s - mx);
    float wsum = e;
    #pragma unroll
    for (int o = 16; o > 0; o >>= 1) wsum += __shfl_xor_sync(0xffffffffu, wsum, o);
    __syncthreads();
    if (lane == 0) wred[wid] = wsum;
    __syncthreads();
    float tot = 0.f;
    #pragma unroll
    for (int w = 0; w < 8; w++) tot += wred[w];
    sc[tid] = e * (1.0f / tot);
    __syncthreads();
    // ctx: warp wid covers t in [wid*32, wid*32+32); lane owns d = lane*4..lane*4+3
    {
        float a0 = 0.f, a1 = 0.f, a2 = 0.f, a3 = 0.f;
        const __half* vbase = g_V + (size_t)m*32768 + (size_t)(wid*32)*128 + lane*4;
        #pragma unroll 8
        for (int tt = 0; tt < 32; tt++) {
            uint2 u = *(const uint2*)(vbase + tt*128);
            __half2 v01 = *(__half2*)&u.x;
            __half2 v23 = *(__half2*)&u.y;
            float svc = sc[wid*32 + tt];
            float2 f01 = __half22float2(v01);
            float2 f23 = __half22float2(v23);
            a0 = fmaf(svc, f01.x, a0);
            a1 = fmaf(svc, f01.y, a1);
            a2 = fmaf(svc, f23.x, a2);
            a3 = fmaf(svc, f23.y, a3);
        }
        float4* cp4 = (float4*)(cpart + wid*128 + lane*4);
        *cp4 = make_float4(a0, a1, a2, a3);
    }
    __syncthreads();
    if (tid < 128) {
        float sum = 0.f;
        #pragma unroll
        for (int w = 0; w < 8; w++) sum += cpart[w*128 + tid];
        g_ctx[m*128 + tid] = sum;
    }
}

// ---------------- D-S2: tiled GRU cell + readout (8 m per block, packed f32x2) ----------------
__global__ void __launch_bounds__(384) d_s2(const float* __restrict__ X,
                                            const float* __restrict__ cbih,
                                            const float* __restrict__ cbhh,
                                            const float* __restrict__ readW,
                                            const float* __restrict__ readb,
                                            float* __restrict__ out, int step)
{
    __shared__ float inA[144*8];
    __shared__ float hS [128*8];
    __shared__ float sA[128*8], sB[128*8], sXn[128*8], sHn[128*8], hn[128*8];
    int tid = threadIdx.x; int m0 = blockIdx.x * 8;
    float* y_out = (step & 1) ? g_yA : g_yB;

    for (int i = tid; i < 144*8; i += 384) {
        int mm = i & 7, k = i >> 3;
        inA[i] = (k < 128) ? g_ctx[(m0 + mm)*128 + k] : g_ymix[(m0 + mm)*16 + (k - 128)];
    }
    for (int i = tid; i < 128*8; i += 384) {
        int mm = i & 7, k = i >> 3;
        hS[i] = g_h[(m0 + mm)*128 + k];
    }
    __syncthreads();

    unsigned inbase = (unsigned)__cvta_generic_to_shared(inA);
    unsigned hbase2 = (unsigned)__cvta_generic_to_shared(hS);

    int g = tid;
    unsigned long long x01, x23, x45, x67, h01v, h23v, h45v, h67v;
    unsigned long long gx01 = pack2(cbih[g]);
    unsigned long long gx23 = gx01, gx45 = gx01, gx67 = gx01;
    unsigned long long gh01 = pack2(cbhh[g]);
    unsigned long long gh23 = gh01, gh45 = gh01, gh67 = gh01;
    const float* wi = g_cWihT + g;
    #pragma unroll 8
    for (int k = 0; k < 144; k++) {
        unsigned long long w2 = pack2(wi[(size_t)k*384]);
        unsigned a0 = inbase + (unsigned)(k*32);
        lds_v2u64(a0, x01, x23);
        lds_v2u64(a0 + 16u, x45, x67);
        fma2(gx01, w2, x01); fma2(gx23, w2, x23);
        fma2(gx45, w2, x45); fma2(gx67, w2, x67);
    }
    const float* wh = g_cWhhT + g;
    #pragma unroll 8
    for (int k = 0; k < 128; k++) {
        unsigned long long w2 = pack2(wh[(size_t)k*384]);
        unsigned a0 = hbase2 + (unsigned)(k*32);
        lds_v2u64(a0, h01v, h23v);
        lds_v2u64(a0 + 16u, h45v, h67v);
        fma2(gh01, w2, h01v); fma2(gh23, w2, h23v);
        fma2(gh45, w2, h45v); fma2(gh67, w2, h67v);
    }
    float gxv[8], ghv[8];
    unpack2(gx01, gxv[0], gxv[1]); unpack2(gx23, gxv[2], gxv[3]);
    unpack2(gx45, gxv[4], gxv[5]); unpack2(gx67, gxv[6], gxv[7]);
    unpack2(gh01, ghv[0], ghv[1]); unpack2(gh23, ghv[2], ghv[3]);
    unpack2(gh45, ghv[4], ghv[5]); unpack2(gh67, ghv[6], ghv[7]);
    if (g < 128) {
        #pragma unroll
        for (int mm = 0; mm < 8; mm++) sA[g*8 + mm] = gxv[mm] + ghv[mm];
    } else if (g < 256) {
        #pragma unroll
        for (int mm = 0; mm < 8; mm++) sB[(g-128)*8 + mm] = gxv[mm] + ghv[mm];
    } else {
        #pragma unroll
        for (int mm = 0; mm < 8; mm++) { sXn[(g-256)*8 + mm] = gxv[mm]; sHn[(g-256)*8 + mm] = ghv[mm]; }
    }
    __syncthreads();
    if (g < 128) {
        #pragma unroll
        for (int mm = 0; mm < 8; mm++) {
            float r  = sigm(sA[g*8 + mm]);
            float z  = sigm(sB[g*8 + mm]);
            float nn = tanhf(sXn[g*8 + mm] + r*sHn[g*8 + mm]);
            float hv = (1.f - z)*nn + z*hS[g*8 + mm];
            g_h[(m0 + mm)*128 + g] = hv;
            hn[g*8 + mm] = hv;
        }
    }
    __syncthreads();
    if (g < 128) {
        int c = g >> 3, r8 = g & 7;
        float a[8];
        #pragma unroll
        for (int mm = 0; mm < 8; mm++) a[mm] = 0.f;
        const float* rw = readW + c*128 + r8*16;
        #pragma unroll
        for (int i = 0; i < 16; i++) {
            float w = rw[i];
            const float* hp = hn + (r8*16 + i)*8;
            #pragma unroll
            for (int mm = 0; mm < 8; mm++) a[mm] = fmaf(w, hp[mm], a[mm]);
        }
        #pragma unroll
        for (int mm = 0; mm < 8; mm++) {
            a[mm] += __shfl_down_sync(0xffffffffu, a[mm], 4, 8);
            a[mm] += __shfl_down_sync(0xffffffffu, a[mm], 2, 8);
            a[mm] += __shfl_down_sync(0xffffffffu, a[mm], 1, 8);
        }
        if (r8 == 0) {
            float rb = readb[c];
            #pragma unroll
            for (int mm = 0; mm < 8; mm++) {
                int mc = (m0 + mm)*16 + c;
                float yt = a[mm] + rb + inA[(128 + c)*8 + mm];
                y_out[mc] = yt;
                float vv = X[(size_t)mc*256 + 255] + yt;
                out[mc*32 + step] = vv;
                if (step == 0) out[524288 + mc] = vv;
            }
        }
    }
}

// ---------------- host launch ----------------
extern "C" void kernel_launch(void* const* d_in, const int* in_sizes, int n_in,
                              void* d_out, int out_size)
{
    const float* X      = (const float*)d_in[0];
    const int*   phases = (const int*)  d_in[1];
    const float* gWih   = (const float*)d_in[2];
    const float* gWhh   = (const float*)d_in[3];
    const float* gbih   = (const float*)d_in[4];
    const float* gbhh   = (const float*)d_in[5];
    const float* lng    = (const float*)d_in[6];
    const float* lnb    = (const float*)d_in[7];
    const float* tW     = (const float*)d_in[8];
    const float* tb     = (const float*)d_in[9];
    const float* S      = (const float*)d_in[10];
    const float* G      = (const float*)d_in[11];
    const float* Wself  = (const float*)d_in[12];
    const float* Wneigh = (const float*)d_in[13];
    const float* cWih   = (const float*)d_in[14];
    const float* cWhh   = (const float*)d_in[15];
    const float* cbih   = (const float*)d_in[16];
    const float* cbhh   = (const float*)d_in[17];
    const float* readW  = (const float*)d_in[18];
    const float* readb  = (const float*)d_in[19];
    const float* Wk     = (const float*)d_in[20];
    const float* Wv     = (const float*)d_in[21];
    const float* ltau   = (const float*)d_in[22];
    float* out = (float*)d_out;

    const int k2_smem = K2_SMEM_FLOATS * (int)sizeof(float);
    const int k3_smem = 2 * 128 * 168 * (int)sizeof(__half);  // 86016
    const int k5_smem = 2 * 128 * 136 * (int)sizeof(__half);  // 69632
    cudaFuncSetAttribute(k2_gru, cudaFuncAttributeMaxDynamicSharedMemorySize, k2_smem);
    cudaFuncSetAttribute(k3_hgemm, cudaFuncAttributeMaxDynamicSharedMemorySize, k3_smem);
    cudaFuncSetAttribute(k5_hgemm, cudaFuncAttributeMaxDynamicSharedMemorySize, k5_smem);

    k0_prep<<<1, 256>>>(Wneigh, Wself, Wk, Wv, S, G, tW, tb, ltau);
    {
        int total = 16*384*128 + 384*144 + 384*128;
        k_trans<<<(total + 255)/256, 256>>>(gWhh, cWih, cWhh);
    }
    k2_gru<<<128, 384, k2_smem>>>(X, gWih, gbih, gbhh, lng, lnb);
    k3_hgemm<<<dim3(2048, 2), 256, k3_smem>>>();
    k4_mix<<<dim3(32, 64), 256>>>(phases);
    k5_hgemm<<<dim3(2048, 2), 256, k5_smem>>>();
    k6_init<<<512, 256>>>();
    for (int s = 0; s < 32; s++) {
        d_s1<<<1024, 256>>>(phases, s);
        d_s2<<<128, 384>>>(X, cbih, cbhh, readW, readb, out, s);
    }
    (void)in_sizes; (void)n_in; (void)out_size;
}

// round 12
// speedup vs baseline: 1.3605x; 1.3605x over previous
#include <cuda_runtime.h>
#include <cuda_fp16.h>
#include <cstdint>

// ---------------- problem constants ----------------
// B=64 N=16 C=16 T=256 DH=128 DT=8 DP=128 TOUT=32 P=4 DIN=136

// ---------------- scratch (static device arrays; no allocation) ----------------
__device__ __half g_Hc [64u*16u*256u*144u];  // [row][144] fp16, cols 136..143 = 0
__device__ __half g_P  [64u*16u*256u*256u];  // [row][0:128]=Hc*Wn^T, [128:256]=Hc*Wself^T
__device__ __half g_Z  [64u*16u*256u*128u];  // [row][128] fp16
__device__ __half g_K [1024u*128u*256u];     // [m][d][t]  fp16 (transposed for decoder)
__device__ __half g_V [1024u*256u*128u];     // [m][t][d]  fp16
__device__ __half g_WhhH[16*384*128];        // [n][g][k] fp16 (original layout)
__device__ __half g_WcatH[256*144];          // rows 0..127 = Wn/sigma, 128..255 = W_self
__device__ __half g_WkvH [256*128];          // rows 0..127 = Wk, 128..255 = Wv
__device__ float g_cWihT[144*384];           // [k][g]
__device__ float g_cWhhT[128*384];           // [k][g]
__device__ float g_Aph  [4*16*16];
__device__ float g_utab [256*8];
__device__ float g_h   [1024*128];
__device__ float g_yA  [1024*16];
__device__ float g_yB  [1024*16];
__device__ float g_ctx [1024*128];
__device__ float g_ymix[1024*16];
__device__ float g_scale[1];

__device__ __forceinline__ float sigm(float x){ return 1.0f/(1.0f+expf(-x)); }

__device__ __forceinline__ void mma16816(float* c, const uint32_t* a, const uint32_t* b) {
    asm volatile("mma.sync.aligned.m16n8k16.row.col.f32.f16.f16.f32 "
        "{%0,%1,%2,%3}, {%4,%5,%6,%7}, {%8,%9}, {%0,%1,%2,%3};"
        : "+f"(c[0]), "+f"(c[1]), "+f"(c[2]), "+f"(c[3])
        : "r"(a[0]), "r"(a[1]), "r"(a[2]), "r"(a[3]), "r"(b[0]), "r"(b[1]));
}

// packed fp32x2 helpers
__device__ __forceinline__ unsigned long long pack2(float x) {
    unsigned long long r;
    asm("mov.b64 %0, {%1, %1};" : "=l"(r) : "f"(x));
    return r;
}
__device__ __forceinline__ void fma2(unsigned long long& acc, unsigned long long a, unsigned long long b) {
    asm("fma.rn.f32x2 %0, %1, %2, %0;" : "+l"(acc) : "l"(a), "l"(b));
}
__device__ __forceinline__ void lds_v2u64(unsigned addr, unsigned long long& lo, unsigned long long& hi) {
    asm volatile("ld.shared.v2.u64 {%0, %1}, [%2];" : "=l"(lo), "=l"(hi) : "r"(addr));
}
__device__ __forceinline__ void unpack2(unsigned long long p, float& lo, float& hi) {
    asm("mov.b64 {%0, %1}, %2;" : "=f"(lo), "=f"(hi) : "l"(p));
}

// ---------------- K0: spectral norm, phase graphs, u table, weight packs ----------------
__global__ void __launch_bounds__(256) k0_prep(
    const float* __restrict__ Wneigh, const float* __restrict__ Wself,
    const float* __restrict__ Wk, const float* __restrict__ Wv,
    const float* __restrict__ S, const float* __restrict__ G,
    const float* __restrict__ tW, const float* __restrict__ tb,
    const float* __restrict__ ltau)
{
    __shared__ float u[128], v[136], red[256], sig;
    int tid = threadIdx.x;
    if (tid < 128) u[tid] = 1.0f / sqrtf(128.0f);
    __syncthreads();
    for (int it = 0; it < 15; it++) {
        float vv = 0.f;
        if (tid < 136) { float s = 0.f; for (int i = 0; i < 128; i++) s += Wneigh[i*136+tid]*u[i]; vv = s; }
        red[tid] = (tid < 136) ? vv*vv : 0.f; __syncthreads();
        for (int o = 128; o > 0; o >>= 1) { if (tid < o) red[tid] += red[tid+o]; __syncthreads(); }
        float nv = sqrtf(red[0]); __syncthreads();
        if (tid < 136) v[tid] = vv / nv;
        __syncthreads();
        float uu = 0.f;
        if (tid < 128) { float s = 0.f; for (int j = 0; j < 136; j++) s += Wneigh[tid*136+j]*v[j]; uu = s; }
        red[tid] = (tid < 128) ? uu*uu : 0.f; __syncthreads();
        for (int o = 128; o > 0; o >>= 1) { if (tid < o) red[tid] += red[tid+o]; __syncthreads(); }
        float nu = sqrtf(red[0]); __syncthreads();
        if (tid < 128) u[tid] = uu / nu;
        __syncthreads();
    }
    {
        float p = 0.f;
        if (tid < 128) { float s = 0.f; for (int j = 0; j < 136; j++) s += Wneigh[tid*136+j]*v[j]; p = u[tid]*s; }
        red[tid] = p; __syncthreads();
        for (int o = 128; o > 0; o >>= 1) { if (tid < o) red[tid] += red[tid+o]; __syncthreads(); }
        if (tid == 0) sig = red[0];
        __syncthreads();
    }
    float inv = 1.0f / sig;
    for (int i = tid; i < 128*144; i += 256) {
        int r = i / 144, cidx = i % 144;
        float wn_ = (cidx < 136) ? Wneigh[r*136 + cidx]*inv : 0.f;
        float ws_ = (cidx < 136) ? Wself[r*136 + cidx] : 0.f;
        g_WcatH[i] = __float2half(wn_);
        g_WcatH[128*144 + i] = __float2half(ws_);
    }
    for (int i = tid; i < 128*128; i += 256) {
        g_WkvH[i] = __float2half(Wk[i]);
        g_WkvH[16384 + i] = __float2half(Wv[i]);
    }
    for (int i = tid; i < 256*8;   i += 256) { int t = i >> 3, j = i & 7;
        g_utab[i] = tanhf(((float)t * (1.0f/255.0f)) * tW[j] + tb[j]); }
    if (tid == 0) g_scale[0] = expf(ltau[0]);
    if (tid < 4) {
        int p = tid; float gg[16]; float gs = 0.f;
        for (int i = 0; i < 16; i++) { float x = G[p*16+i]; float sp = log1pf(expf(x)) + 1e-6f; gg[i] = sp; gs += sp; }
        float gn = 16.0f / fmaxf(gs, 1e-6f);
        for (int i = 0; i < 16; i++) {
            float den = 0.f;
            for (int j = 0; j < 16; j++) { float sv = (i==j) ? 0.f : S[p*256+i*16+j]; den += fabsf(sv); }
            den = fmaxf(den, 1e-6f);
            float gi = gg[i]*gn;
            for (int j = 0; j < 16; j++) { float sv = (i==j) ? 0.f : S[p*256+i*16+j];
                g_Aph[p*256+i*16+j] = sv/den*gi; }
        }
    }
}

// ---------------- weight packs/transposes ----------------
__global__ void k_trans(const float* __restrict__ Whh,
                        const float* __restrict__ cWih, const float* __restrict__ cWhh)
{
    int i = blockIdx.x*256 + threadIdx.x;
    const int T1 = 16*384*128, T2 = 384*144, T3 = 384*128;
    if (i < T1) {
        g_WhhH[i] = __float2half(Whh[i]);   // [n][g][k] direct
    } else if (i < T1 + T2) {
        int j = i - T1; int gg = j / 144, k = j % 144;
        g_cWihT[k*384 + gg] = cWih[j];
    } else if (i < T1 + T2 + T3) {
        int j = i - T1 - T2; int gg = j / 128, k = j % 128;
        g_cWhhT[k*384 + gg] = cWhh[j];
    }
}

// ---------------- K2: GRU scan, Whh@h via HMMA, fused Gx + LN, writes Hc fp16 ----------------
// smem float layout:
//  h32 [0,1024)  sA [1024,2048) sB [2048,3072) sXn [3072,4096) sHn [4096,5120)
//  ghS [5120,8192)  Wih_s [8192,14336)  Xs [14336,22528)
//  lg [22528,22656) lb [22656,22784) red1 [22784,22816) red2 [22816,22848)
//  then half region: WhhH 384x136 halfs, h16 8x136 halfs
#define K2_SMEM_BYTES (22848*4 + (384*136 + 8*136)*2)
__global__ void __launch_bounds__(384) k2_gru(const float* __restrict__ X,
                                              const float* __restrict__ Wih,
                                              const float* __restrict__ bih,
                                              const float* __restrict__ bhh,
                                              const float* __restrict__ lng,
                                              const float* __restrict__ lnb)
{
    extern __shared__ float sm[];
    float* h32   = sm;
    float* sA    = sm + 1024;
    float* sB    = sm + 2048;
    float* sXn   = sm + 3072;
    float* sHn   = sm + 4096;
    float* ghS   = sm + 5120;
    float* Wih_s = sm + 8192;
    float* Xs    = sm + 14336;
    float* lg    = sm + 22528;
    float* lb    = sm + 22656;
    float* red1  = sm + 22784;
    float* red2  = sm + 22816;
    __half* WhhS = (__half*)(sm + 22848);
    __half* h16  = WhhS + 384*136;

    int g = threadIdx.x;
    int n = blockIdx.x >> 3, bg = blockIdx.x & 7;
    if (g < 128) { lg[g] = lng[g]; lb[g] = lnb[g]; }
    for (int i = g; i < 1024; i += 384) h32[i] = 0.f;
    for (int i = g; i < 8*136; i += 384) h16[i] = __float2half(0.f);
    for (int i = g; i < 6144; i += 384) { int g2 = i >> 4, c = i & 15;
        Wih_s[c*384 + g2] = Wih[n*6144 + i]; }
    // Whh fp16 -> smem (pitch 136)
    for (int i = g; i < 384*16; i += 384) {
        int r = i >> 4, c8 = i & 15;
        *(int4*)(WhhS + r*136 + c8*8) = *(const int4*)(g_WhhH + n*49152 + r*128 + c8*8);
    }
    float bhh_g = bhh[n*384 + g];
    float bih_g = bih[n*384 + g];
    unsigned xbase = (unsigned)__cvta_generic_to_shared(Xs);
    unsigned long long bih2 = pack2(bih_g);
    int w = g >> 5, l = g & 31;
    int lr = l >> 2, lk = (l & 3)*2;
    const __half* a0base = WhhS + (w*32 + lr)*136 + lk;
    const __half* a1base = a0base + 16*136;
    const __half* bbase  = h16 + lr*136 + lk;
    __syncthreads();

    for (int t = 0; t < 256; t++) {
        int tc = t & 63;
        if (tc == 0) {
            __syncthreads();
            for (int i = g; i < 8192; i += 384) {
                int b = i >> 10, r = i & 1023, c = r >> 6, tcc = r & 63;
                Xs[c*512 + tcc*8 + b] = X[(size_t)((bg*8 + b)*16 + n)*4096 + c*256 + t + tcc];
            }
            __syncthreads();
        }
        // gx via packed FFMA2
        unsigned long long g01 = bih2, g23 = bih2, g45 = bih2, g67 = bih2;
        #pragma unroll
        for (int c = 0; c < 16; c++) {
            unsigned long long w2 = pack2(Wih_s[c*384 + g]);
            unsigned long long x01, x23, x45, x67;
            unsigned xaddr = xbase + (unsigned)(c*512 + tc*8) * 4u;
            lds_v2u64(xaddr, x01, x23);
            lds_v2u64(xaddr + 16u, x45, x67);
            fma2(g01, w2, x01); fma2(g23, w2, x23);
            fma2(g45, w2, x45); fma2(g67, w2, x67);
        }
        float gx[8];
        unpack2(g01, gx[0], gx[1]); unpack2(g23, gx[2], gx[3]);
        unpack2(g45, gx[4], gx[5]); unpack2(g67, gx[6], gx[7]);
        // gh = Whh @ h via HMMA: warp w covers gate rows [32w, 32w+32)
        {
            float c0[4], c1[4];
            #pragma unroll
            for (int q = 0; q < 4; q++) { c0[q] = 0.f; c1[q] = 0.f; }
            #pragma unroll
            for (int kc = 0; kc < 8; kc++) {
                int k0 = kc*16;
                uint32_t b2[2], a[4];
                b2[0] = *(const uint32_t*)(bbase + k0);
                b2[1] = *(const uint32_t*)(bbase + k0 + 8);
                a[0] = *(const uint32_t*)(a0base + k0);
                a[1] = *(const uint32_t*)(a0base + 8*136 + k0);
                a[2] = *(const uint32_t*)(a0base + k0 + 8);
                a[3] = *(const uint32_t*)(a0base + 8*136 + k0 + 8);
                mma16816(c0, a, b2);
                a[0] = *(const uint32_t*)(a1base + k0);
                a[1] = *(const uint32_t*)(a1base + 8*136 + k0);
                a[2] = *(const uint32_t*)(a1base + k0 + 8);
                a[3] = *(const uint32_t*)(a1base + 8*136 + k0 + 8);
                mma16816(c1, a, b2);
            }
            int r0 = w*32 + lr;
            *(float2*)(ghS + r0*8 + lk)      = make_float2(c0[0], c0[1]);
            *(float2*)(ghS + (r0+8)*8 + lk)  = make_float2(c0[2], c0[3]);
            *(float2*)(ghS + (r0+16)*8 + lk) = make_float2(c1[0], c1[1]);
            *(float2*)(ghS + (r0+24)*8 + lk) = make_float2(c1[2], c1[3]);
        }
        __syncthreads();
        // gate pre-activations
        if (g < 128) {
            #pragma unroll
            for (int b = 0; b < 8; b++) sA[g*8 + b] = gx[b] + ghS[g*8 + b] + bhh_g;
        } else if (g < 256) {
            #pragma unroll
            for (int b = 0; b < 8; b++) sB[(g-128)*8 + b] = gx[b] + ghS[g*8 + b] + bhh_g;
        } else {
            #pragma unroll
            for (int b = 0; b < 8; b++) { sXn[(g-256)*8 + b] = gx[b]; sHn[(g-256)*8 + b] = ghS[g*8 + b] + bhh_g; }
        }
        __syncthreads();
        float hnew[8];
        if (g < 128) {
            float s1[8], s2[8];
            #pragma unroll
            for (int b = 0; b < 8; b++) {
                float r  = sigm(sA[g*8 + b]);
                float z  = sigm(sB[g*8 + b]);
                float nn = tanhf(sXn[g*8 + b] + r*sHn[g*8 + b]);
                float hv = (1.f - z)*nn + z*h32[g*8 + b];
                hnew[b] = hv; h32[g*8 + b] = hv;
                h16[b*136 + g] = __float2half(hv);
                s1[b] = hv; s2[b] = hv*hv;
            }
            #pragma unroll
            for (int off = 16; off > 0; off >>= 1) {
                #pragma unroll
                for (int b = 0; b < 8; b++) {
                    s1[b] += __shfl_down_sync(0xffffffffu, s1[b], off);
                    s2[b] += __shfl_down_sync(0xffffffffu, s2[b], off);
                }
            }
            if ((g & 31) == 0) { int wq = g >> 5;
                #pragma unroll
                for (int b = 0; b < 8; b++) { red1[wq*8 + b] = s1[b]; red2[wq*8 + b] = s2[b]; }
            }
        }
        __syncthreads();
        if (g < 128) {
            #pragma unroll
            for (int b = 0; b < 8; b++) {
                float mean = (red1[b] + red1[8+b] + red1[16+b] + red1[24+b]) * 0.0078125f;
                float msq  = (red2[b] + red2[8+b] + red2[16+b] + red2[24+b]) * 0.0078125f;
                float var  = msq - mean*mean;
                float rstd = rsqrtf(var + 1e-5f);
                int bm = (bg*8 + b)*16 + n;
                g_Hc[((size_t)bm*256 + t)*144 + g] = __float2half((hnew[b] - mean)*rstd*lg[g] + lb[g]);
            }
        } else if (g < 136) {
            float uv = g_utab[t*8 + (g - 128)];
            #pragma unroll
            for (int b = 0; b < 8; b++) {
                int bm = (bg*8 + b)*16 + n;
                g_Hc[((size_t)bm*256 + t)*144 + g] = __float2half(uv);
            }
        } else if (g < 144) {
            #pragma unroll
            for (int b = 0; b < 8; b++) {
                int bm = (bg*8 + b)*16 + n;
                g_Hc[((size_t)bm*256 + t)*144 + g] = __float2half(0.f);
            }
        }
        __syncthreads();
    }
}

// ---------------- K3: P = Hc @ Wcat^T via HMMA  (262144 x 144) @ (144 x 256) ----------------
__global__ void __launch_bounds__(256) k3_hgemm()
{
    extern __shared__ __half smh[];
    const int PITCH = 168;
    __half* As = smh;
    __half* Bs = smh + 128*PITCH;
    int tid = threadIdx.x;
    size_t row0 = (size_t)blockIdx.x * 128;
    int col0 = blockIdx.y * 128;
    for (int i = tid; i < 128*18; i += 256) {
        int r = i / 18, c = i % 18;
        *(int4*)(As + r*PITCH + c*8) = *(const int4*)(g_Hc + (row0 + r)*144 + c*8);
    }
    for (int i = tid; i < 128*18; i += 256) {
        int r = i / 18, c = i % 18;
        *(int4*)(Bs + r*PITCH + c*8) = *(const int4*)(g_WcatH + (size_t)(col0 + r)*144 + c*8);
    }
    __syncthreads();
    int w = tid >> 5, l = tid & 31;
    int wm = w & 1, wn = w >> 1;
    int lr = l >> 2, lk = (l & 3)*2;
    float c[4][4][4];
    #pragma unroll
    for (int mi = 0; mi < 4; mi++)
        #pragma unroll
        for (int ni = 0; ni < 4; ni++)
            #pragma unroll
            for (int q = 0; q < 4; q++) c[mi][ni][q] = 0.f;
    #pragma unroll
    for (int kc = 0; kc < 9; kc++) {
        int k0 = kc*16;
        uint32_t a[4][4], b[4][2];
        #pragma unroll
        for (int mi = 0; mi < 4; mi++) {
            const __half* ap = As + (wm*64 + mi*16 + lr)*PITCH + k0 + lk;
            a[mi][0] = *(const uint32_t*)(ap);
            a[mi][1] = *(const uint32_t*)(ap + 8*PITCH);
            a[mi][2] = *(const uint32_t*)(ap + 8);
            a[mi][3] = *(const uint32_t*)(ap + 8*PITCH + 8);
        }
        #pragma unroll
        for (int ni = 0; ni < 4; ni++) {
            const __half* bp = Bs + (wn*32 + ni*8 + lr)*PITCH + k0 + lk;
            b[ni][0] = *(const uint32_t*)(bp);
            b[ni][1] = *(const uint32_t*)(bp + 8);
        }
        #pragma unroll
        for (int mi = 0; mi < 4; mi++)
            #pragma unroll
            for (int ni = 0; ni < 4; ni++)
                mma16816(c[mi][ni], a[mi], b[ni]);
    }
    #pragma unroll
    for (int mi = 0; mi < 4; mi++) {
        size_t ra = row0 + wm*64 + mi*16 + lr;
        #pragma unroll
        for (int ni = 0; ni < 4; ni++) {
            int cc = col0 + wn*32 + ni*8 + lk;
            *(__half2*)(g_P + ra*256 + cc)     = __floats2half2_rn(c[mi][ni][0], c[mi][ni][1]);
            *(__half2*)(g_P + (ra+8)*256 + cc) = __floats2half2_rn(c[mi][ni][2], c[mi][ni][3]);
        }
    }
}

// ---------------- K4: graph mix + self + leaky -> Z (fp16 IO, scalar) ----------------
__global__ void __launch_bounds__(256) k4_mix(const int* __restrict__ phases)
{
    __shared__ float Am[256], sP[2048];
    int tid = threadIdx.x; int b = blockIdx.y; int t0 = blockIdx.x*8;
    Am[tid] = g_Aph[phases[b]*256 + tid];
    for (int tc = 0; tc < 8; tc++) {
        int t = t0 + tc;
        __syncthreads();
        for (int idx = tid; idx < 2048; idx += 256) { int j = idx >> 7, d = idx & 127;
            sP[idx] = __half2float(g_P[((size_t)(b*16 + j)*256 + t)*256 + d]); }
        __syncthreads();
        for (int idx = tid; idx < 2048; idx += 256) {
            int i = idx >> 7, d = idx & 127;
            size_t row = (size_t)(b*16 + i)*256 + t;
            float accv = __half2float(g_P[row*256 + 128 + d]);
            #pragma unroll
            for (int j = 0; j < 16; j++) accv = fmaf(Am[i*16 + j], sP[j*128 + d], accv);
            g_Z[row*128 + d] = __float2half((accv >= 0.f) ? accv : 0.1f*accv);
        }
    }
}

// ---------------- K5: K|V = Z @ Wkv^T via HMMA; K fp16 [m][d][t], V fp16 [m][t][d] ----------------
__global__ void __launch_bounds__(256) k5_hgemm()
{
    extern __shared__ __half smh[];
    const int PITCH = 136;
    __half* As = smh;
    __half* Bs = smh + 128*PITCH;
    int tid = threadIdx.x;
    size_t row0 = (size_t)blockIdx.x * 128;
    int col0 = blockIdx.y * 128;
    for (int i = tid; i < 128*16; i += 256) {
        int r = i >> 4, c = i & 15;
        *(int4*)(As + r*PITCH + c*8) = *(const int4*)(g_Z + (row0 + r)*128 + c*8);
    }
    for (int i = tid; i < 128*16; i += 256) {
        int r = i >> 4, c = i & 15;
        *(int4*)(Bs + r*PITCH + c*8) = *(const int4*)(g_WkvH + (size_t)(col0 + r)*128 + c*8);
    }
    __syncthreads();
    int w = tid >> 5, l = tid & 31;
    int wm = w & 1, wn = w >> 1;
    int lr = l >> 2, lk = (l & 3)*2;
    float c[4][4][4];
    #pragma unroll
    for (int mi = 0; mi < 4; mi++)
        #pragma unroll
        for (int ni = 0; ni < 4; ni++)
            #pragma unroll
            for (int q = 0; q < 4; q++) c[mi][ni][q] = 0.f;
    #pragma unroll
    for (int kc = 0; kc < 8; kc++) {
        int k0 = kc*16;
        uint32_t a[4][4], b[4][2];
        #pragma unroll
        for (int mi = 0; mi < 4; mi++) {
            const __half* ap = As + (wm*64 + mi*16 + lr)*PITCH + k0 + lk;
            a[mi][0] = *(const uint32_t*)(ap);
            a[mi][1] = *(const uint32_t*)(ap + 8*PITCH);
            a[mi][2] = *(const uint32_t*)(ap + 8);
            a[mi][3] = *(const uint32_t*)(ap + 8*PITCH + 8);
        }
        #pragma unroll
        for (int ni = 0; ni < 4; ni++) {
            const __half* bp = Bs + (wn*32 + ni*8 + lr)*PITCH + k0 + lk;
            b[ni][0] = *(const uint32_t*)(bp);
            b[ni][1] = *(const uint32_t*)(bp + 8);
        }
        #pragma unroll
        for (int mi = 0; mi < 4; mi++)
            #pragma unroll
            for (int ni = 0; ni < 4; ni++)
                mma16816(c[mi][ni], a[mi], b[ni]);
    }
    #pragma unroll
    for (int mi = 0; mi < 4; mi++) {
        size_t ra = row0 + wm*64 + mi*16 + lr;
        size_t rb = ra + 8;
        int ma = (int)(ra >> 8), ta = (int)(ra & 255);
        int tb2 = (int)(rb & 255);
        #pragma unroll
        for (int ni = 0; ni < 4; ni++) {
            int cc = wn*32 + ni*8 + lk;
            if (blockIdx.y == 0) {
                __half* kb = g_K + (size_t)ma*32768;
                kb[(size_t)cc*256 + ta]     = __float2half(c[mi][ni][0]);
                kb[(size_t)(cc+1)*256 + ta] = __float2half(c[mi][ni][1]);
                kb[(size_t)cc*256 + tb2]     = __float2half(c[mi][ni][2]);
                kb[(size_t)(cc+1)*256 + tb2] = __float2half(c[mi][ni][3]);
            } else {
                *(__half2*)(g_V + ra*128 + cc) = __floats2half2_rn(c[mi][ni][0], c[mi][ni][1]);
                *(__half2*)(g_V + rb*128 + cc) = __floats2half2_rn(c[mi][ni][2], c[mi][ni][3]);
            }
        }
    }
}

// ---------------- K6: decode init ----------------
__global__ void k6_init()
{
    int i = blockIdx.x*256 + threadIdx.x;
    if (i < 1024*128) { int m = i >> 7, d = i & 127;
        g_h[i] = __half2float(g_Z[((size_t)m*256 + 255)*128 + d]); }
    if (i < 1024*16) { g_yA[i] = 0.f; g_yB[i] = 0.f; }
}

// ---------------- D-S1: y-mix + attention -> g_ctx, g_ymix ----------------
__global__ void __launch_bounds__(256) d_s1(const int* __restrict__ phases, int step)
{
    __shared__ float ys[256], h_s[128], sc[256], arow[16], wred[8];
    int tid = threadIdx.x; int m = blockIdx.x; int b = m >> 4, n = m & 15;
    const float* y_in = (step & 1) ? g_yB : g_yA;
    ys[tid] = y_in[b*256 + tid];
    if (tid < 16) arow[tid] = g_Aph[phases[b]*256 + n*16 + tid];
    if (tid < 128) h_s[tid] = g_h[m*128 + tid];
    __syncthreads();
    if (tid < 16) {
        float a = 0.f;
        #pragma unroll
        for (int j = 0; j < 16; j++) a = fmaf(arow[j], ys[j*16 + tid], a);
        g_ymix[m*16 + tid] = ys[n*16 + tid] + 0.3f*a;
    }
    const __half* kp = g_K + (size_t)m*32768 + tid;
    float s = 0.f;
    #pragma unroll 8
    for (int d = 0; d < 128; d++) s = fmaf(__half2float(kp[(size_t)d*256]), h_s[d], s);
    s *= g_scale[0];
    int lane = tid & 31, wid = tid >> 5;
    float wm = s;
    #pragma unroll
    for (int o = 16; o > 0; o >>= 1) wm = fmaxf(wm, __shfl_xor_sync(0xffffffffu, wm, o));
    if (lane == 0) wred[wid] = wm;
    __syncthreads();
    float mx = wred[0];
    #pragma unroll
    for (int w = 1; w < 8; w++) mx = fmaxf(mx, wred[w]);
    float e = expf(s - mx);
    float wsum = e;
    #pragma unroll
    for (int o = 16; o > 0; o >>= 1) wsum += __shfl_xor_sync(0xffffffffu, wsum, o);
    __syncthreads();
    if (lane == 0) wred[wid] = wsum;
    __syncthreads();
    float tot = 0.f;
    #pragma unroll
    for (int w = 0; w < 8; w++) tot += wred[w];
    sc[tid] = e * (1.0f / tot);
    __syncthreads();
    int d = tid & 127, half = tid >> 7;
    const __half* vp = g_V + ((size_t)m*256 + half*128)*128 + d;
    float accv = 0.f;
    #pragma unroll 8
    for (int tt = 0; tt < 128; tt++) accv = fmaf(sc[half*128 + tt], __half2float(vp[(size_t)tt*128]), accv);
    __syncthreads();
    ys[tid] = accv;
    __syncthreads();
    if (tid < 128) g_ctx[m*128 + tid] = ys[tid] + ys[tid + 128];
}

// ---------------- D-S2: tiled GRU cell + readout (8 m per block, packed f32x2) ----------------
__global__ void __launch_bounds__(384) d_s2(const float* __restrict__ X,
                                            const float* __restrict__ cbih,
                                            const float* __restrict__ cbhh,
                                            const float* __restrict__ readW,
                                            const float* __restrict__ readb,
                                            float* __restrict__ out, int step)
{
    __shared__ float inA[144*8];
    __shared__ float hS [128*8];
    __shared__ float sA[128*8], sB[128*8], sXn[128*8], sHn[128*8], hn[128*8];
    int tid = threadIdx.x; int m0 = blockIdx.x * 8;
    float* y_out = (step & 1) ? g_yA : g_yB;

    for (int i = tid; i < 144*8; i += 384) {
        int mm = i & 7, k = i >> 3;
        inA[i] = (k < 128) ? g_ctx[(m0 + mm)*128 + k] : g_ymix[(m0 + mm)*16 + (k - 128)];
    }
    for (int i = tid; i < 128*8; i += 384) {
        int mm = i & 7, k = i >> 3;
        hS[i] = g_h[(m0 + mm)*128 + k];
    }
    __syncthreads();

    unsigned inbase = (unsigned)__cvta_generic_to_shared(inA);
    unsigned hbase2 = (unsigned)__cvta_generic_to_shared(hS);

    int g = tid;
    unsigned long long x01, x23, x45, x67, h01v, h23v, h45v, h67v;
    unsigned long long gx01 = pack2(cbih[g]);
    unsigned long long gx23 = gx01, gx45 = gx01, gx67 = gx01;
    unsigned long long gh01 = pack2(cbhh[g]);
    unsigned long long gh23 = gh01, gh45 = gh01, gh67 = gh01;
    const float* wi = g_cWihT + g;
    #pragma unroll 8
    for (int k = 0; k < 144; k++) {
        unsigned long long w2 = pack2(wi[(size_t)k*384]);
        unsigned a0 = inbase + (unsigned)(k*32);
        lds_v2u64(a0, x01, x23);
        lds_v2u64(a0 + 16u, x45, x67);
        fma2(gx01, w2, x01); fma2(gx23, w2, x23);
        fma2(gx45, w2, x45); fma2(gx67, w2, x67);
    }
    const float* wh = g_cWhhT + g;
    #pragma unroll 8
    for (int k = 0; k < 128; k++) {
        unsigned long long w2 = pack2(wh[(size_t)k*384]);
        unsigned a0 = hbase2 + (unsigned)(k*32);
        lds_v2u64(a0, h01v, h23v);
        lds_v2u64(a0 + 16u, h45v, h67v);
        fma2(gh01, w2, h01v); fma2(gh23, w2, h23v);
        fma2(gh45, w2, h45v); fma2(gh67, w2, h67v);
    }
    float gxv[8], ghv[8];
    unpack2(gx01, gxv[0], gxv[1]); unpack2(gx23, gxv[2], gxv[3]);
    unpack2(gx45, gxv[4], gxv[5]); unpack2(gx67, gxv[6], gxv[7]);
    unpack2(gh01, ghv[0], ghv[1]); unpack2(gh23, ghv[2], ghv[3]);
    unpack2(gh45, ghv[4], ghv[5]); unpack2(gh67, ghv[6], ghv[7]);
    if (g < 128) {
        #pragma unroll
        for (int mm = 0; mm < 8; mm++) sA[g*8 + mm] = gxv[mm] + ghv[mm];
    } else if (g < 256) {
        #pragma unroll
        for (int mm = 0; mm < 8; mm++) sB[(g-128)*8 + mm] = gxv[mm] + ghv[mm];
    } else {
        #pragma unroll
        for (int mm = 0; mm < 8; mm++) { sXn[(g-256)*8 + mm] = gxv[mm]; sHn[(g-256)*8 + mm] = ghv[mm]; }
    }
    __syncthreads();
    if (g < 128) {
        #pragma unroll
        for (int mm = 0; mm < 8; mm++) {
            float r  = sigm(sA[g*8 + mm]);
            float z  = sigm(sB[g*8 + mm]);
            float nn = tanhf(sXn[g*8 + mm] + r*sHn[g*8 + mm]);
            float hv = (1.f - z)*nn + z*hS[g*8 + mm];
            g_h[(m0 + mm)*128 + g] = hv;
            hn[g*8 + mm] = hv;
        }
    }
    __syncthreads();
    if (g < 128) {
        int c = g >> 3, r8 = g & 7;
        float a[8];
        #pragma unroll
        for (int mm = 0; mm < 8; mm++) a[mm] = 0.f;
        const float* rw = readW + c*128 + r8*16;
        #pragma unroll
        for (int i = 0; i < 16; i++) {
            float w = rw[i];
            const float* hp = hn + (r8*16 + i)*8;
            #pragma unroll
            for (int mm = 0; mm < 8; mm++) a[mm] = fmaf(w, hp[mm], a[mm]);
        }
        #pragma unroll
        for (int mm = 0; mm < 8; mm++) {
            a[mm] += __shfl_down_sync(0xffffffffu, a[mm], 4, 8);
            a[mm] += __shfl_down_sync(0xffffffffu, a[mm], 2, 8);
            a[mm] += __shfl_down_sync(0xffffffffu, a[mm], 1, 8);
        }
        if (r8 == 0) {
            float rb = readb[c];
            #pragma unroll
            for (int mm = 0; mm < 8; mm++) {
                int mc = (m0 + mm)*16 + c;
                float yt = a[mm] + rb + inA[(128 + c)*8 + mm];
                y_out[mc] = yt;
                float vv = X[(size_t)mc*256 + 255] + yt;
                out[mc*32 + step] = vv;
                if (step == 0) out[524288 + mc] = vv;
            }
        }
    }
}

// ---------------- host launch ----------------
extern "C" void kernel_launch(void* const* d_in, const int* in_sizes, int n_in,
                              void* d_out, int out_size)
{
    const float* X      = (const float*)d_in[0];
    const int*   phases = (const int*)  d_in[1];
    const float* gWih   = (const float*)d_in[2];
    const float* gWhh   = (const float*)d_in[3];
    const float* gbih   = (const float*)d_in[4];
    const float* gbhh   = (const float*)d_in[5];
    const float* lng    = (const float*)d_in[6];
    const float* lnb    = (const float*)d_in[7];
    const float* tW     = (const float*)d_in[8];
    const float* tb     = (const float*)d_in[9];
    const float* S      = (const float*)d_in[10];
    const float* G      = (const float*)d_in[11];
    const float* Wself  = (const float*)d_in[12];
    const float* Wneigh = (const float*)d_in[13];
    const float* cWih   = (const float*)d_in[14];
    const float* cWhh   = (const float*)d_in[15];
    const float* cbih   = (const float*)d_in[16];
    const float* cbhh   = (const float*)d_in[17];
    const float* readW  = (const float*)d_in[18];
    const float* readb  = (const float*)d_in[19];
    const float* Wk     = (const float*)d_in[20];
    const float* Wv     = (const float*)d_in[21];
    const float* ltau   = (const float*)d_in[22];
    float* out = (float*)d_out;

    const int k2_smem = K2_SMEM_BYTES;
    const int k3_smem = 2 * 128 * 168 * (int)sizeof(__half);  // 86016
    const int k5_smem = 2 * 128 * 136 * (int)sizeof(__half);  // 69632
    cudaFuncSetAttribute(k2_gru, cudaFuncAttributeMaxDynamicSharedMemorySize, k2_smem);
    cudaFuncSetAttribute(k3_hgemm, cudaFuncAttributeMaxDynamicSharedMemorySize, k3_smem);
    cudaFuncSetAttribute(k5_hgemm, cudaFuncAttributeMaxDynamicSharedMemorySize, k5_smem);

    k0_prep<<<1, 256>>>(Wneigh, Wself, Wk, Wv, S, G, tW, tb, ltau);
    {
        int total = 16*384*128 + 384*144 + 384*128;
        k_trans<<<(total + 255)/256, 256>>>(gWhh, cWih, cWhh);
    }
    k2_gru<<<128, 384, k2_smem>>>(X, gWih, gbih, gbhh, lng, lnb);
    k3_hgemm<<<dim3(2048, 2), 256, k3_smem>>>();
    k4_mix<<<dim3(32, 64), 256>>>(phases);
    k5_hgemm<<<dim3(2048, 2), 256, k5_smem>>>();
    k6_init<<<512, 256>>>();
    for (int s = 0; s < 32; s++) {
        d_s1<<<1024, 256>>>(phases, s);
        d_s2<<<128, 384>>>(X, cbih, cbhh, readW, readb, out, s);
    }
    (void)in_sizes; (void)n_in; (void)out_size;
}

// round 13
// speedup vs baseline: 1.9953x; 1.4666x over previous
#include <cuda_runtime.h>
#include <cuda_fp16.h>
#include <cstdint>

// ---------------- problem constants ----------------
// B=64 N=16 C=16 T=256 DH=128 DT=8 DP=128 TOUT=32 P=4 DIN=136

// ---------------- scratch (static device arrays; no allocation) ----------------
__device__ __half g_Hc [64u*16u*256u*144u];  // [row][144] fp16, cols 136..143 = 0
__device__ __half g_P  [64u*16u*256u*256u];  // [row][0:128]=Hc*Wn^T, [128:256]=Hc*Wself^T
__device__ __half g_Z  [64u*16u*256u*128u];  // [row][128] fp16
__device__ __half g_K [1024u*128u*256u];     // [m][d][t]  fp16 (transposed for decoder)
__device__ __half g_V [1024u*256u*128u];     // [m][t][d]  fp16
__device__ __half g_WhhH[16*384*128];        // [n][g][k] fp16
__device__ __half g_WcatH[256*144];          // rows 0..127 = Wn/sigma, 128..255 = W_self
__device__ __half g_WkvH [256*128];          // rows 0..127 = Wk, 128..255 = Wv
__device__ __half g_cWpack[24*17*32*8];      // cell weights, mma-fragment order
__device__ float g_Aph  [4*16*16];
__device__ float g_utab [256*8];
__device__ float g_h   [1024*128];
__device__ float g_yA  [1024*16];
__device__ float g_yB  [1024*16];
__device__ float g_ctx [1024*128];
__device__ float g_ymix[1024*16];
__device__ float g_scale[1];

__device__ __forceinline__ float sigm(float x){ return 1.0f/(1.0f+expf(-x)); }

__device__ __forceinline__ void mma16816(float* c, const uint32_t* a, const uint32_t* b) {
    asm volatile("mma.sync.aligned.m16n8k16.row.col.f32.f16.f16.f32 "
        "{%0,%1,%2,%3}, {%4,%5,%6,%7}, {%8,%9}, {%0,%1,%2,%3};"
        : "+f"(c[0]), "+f"(c[1]), "+f"(c[2]), "+f"(c[3])
        : "r"(a[0]), "r"(a[1]), "r"(a[2]), "r"(a[3]), "r"(b[0]), "r"(b[1]));
}

// packed fp32x2 helpers
__device__ __forceinline__ unsigned long long pack2(float x) {
    unsigned long long r;
    asm("mov.b64 %0, {%1, %1};" : "=l"(r) : "f"(x));
    return r;
}
__device__ __forceinline__ void fma2(unsigned long long& acc, unsigned long long a, unsigned long long b) {
    asm("fma.rn.f32x2 %0, %1, %2, %0;" : "+l"(acc) : "l"(a), "l"(b));
}
__device__ __forceinline__ void lds_v2u64(unsigned addr, unsigned long long& lo, unsigned long long& hi) {
    asm volatile("ld.shared.v2.u64 {%0, %1}, [%2];" : "=l"(lo), "=l"(hi) : "r"(addr));
}
__device__ __forceinline__ void unpack2(unsigned long long p, float& lo, float& hi) {
    asm("mov.b64 {%0, %1}, %2;" : "=f"(lo), "=f"(hi) : "l"(p));
}

// ---------------- K0: spectral norm, phase graphs, u table, weight packs ----------------
__global__ void __launch_bounds__(256) k0_prep(
    const float* __restrict__ Wneigh, const float* __restrict__ Wself,
    const float* __restrict__ Wk, const float* __restrict__ Wv,
    const float* __restrict__ S, const float* __restrict__ G,
    const float* __restrict__ tW, const float* __restrict__ tb,
    const float* __restrict__ ltau)
{
    __shared__ float u[128], v[136], red[256], sig;
    int tid = threadIdx.x;
    if (tid < 128) u[tid] = 1.0f / sqrtf(128.0f);
    __syncthreads();
    for (int it = 0; it < 15; it++) {
        float vv = 0.f;
        if (tid < 136) { float s = 0.f; for (int i = 0; i < 128; i++) s += Wneigh[i*136+tid]*u[i]; vv = s; }
        red[tid] = (tid < 136) ? vv*vv : 0.f; __syncthreads();
        for (int o = 128; o > 0; o >>= 1) { if (tid < o) red[tid] += red[tid+o]; __syncthreads(); }
        float nv = sqrtf(red[0]); __syncthreads();
        if (tid < 136) v[tid] = vv / nv;
        __syncthreads();
        float uu = 0.f;
        if (tid < 128) { float s = 0.f; for (int j = 0; j < 136; j++) s += Wneigh[tid*136+j]*v[j]; uu = s; }
        red[tid] = (tid < 128) ? uu*uu : 0.f; __syncthreads();
        for (int o = 128; o > 0; o >>= 1) { if (tid < o) red[tid] += red[tid+o]; __syncthreads(); }
        float nu = sqrtf(red[0]); __syncthreads();
        if (tid < 128) u[tid] = uu / nu;
        __syncthreads();
    }
    {
        float p = 0.f;
        if (tid < 128) { float s = 0.f; for (int j = 0; j < 136; j++) s += Wneigh[tid*136+j]*v[j]; p = u[tid]*s; }
        red[tid] = p; __syncthreads();
        for (int o = 128; o > 0; o >>= 1) { if (tid < o) red[tid] += red[tid+o]; __syncthreads(); }
        if (tid == 0) sig = red[0];
        __syncthreads();
    }
    float inv = 1.0f / sig;
    for (int i = tid; i < 128*144; i += 256) {
        int r = i / 144, cidx = i % 144;
        float wn_ = (cidx < 136) ? Wneigh[r*136 + cidx]*inv : 0.f;
        float ws_ = (cidx < 136) ? Wself[r*136 + cidx] : 0.f;
        g_WcatH[i] = __float2half(wn_);
        g_WcatH[128*144 + i] = __float2half(ws_);
    }
    for (int i = tid; i < 128*128; i += 256) {
        g_WkvH[i] = __float2half(Wk[i]);
        g_WkvH[16384 + i] = __float2half(Wv[i]);
    }
    for (int i = tid; i < 256*8;   i += 256) { int t = i >> 3, j = i & 7;
        g_utab[i] = tanhf(((float)t * (1.0f/255.0f)) * tW[j] + tb[j]); }
    if (tid == 0) g_scale[0] = expf(ltau[0]);
    if (tid < 4) {
        int p = tid; float gg[16]; float gs = 0.f;
        for (int i = 0; i < 16; i++) { float x = G[p*16+i]; float sp = log1pf(expf(x)) + 1e-6f; gg[i] = sp; gs += sp; }
        float gn = 16.0f / fmaxf(gs, 1e-6f);
        for (int i = 0; i < 16; i++) {
            float den = 0.f;
            for (int j = 0; j < 16; j++) { float sv = (i==j) ? 0.f : S[p*256+i*16+j]; den += fabsf(sv); }
            den = fmaxf(den, 1e-6f);
            float gi = gg[i]*gn;
            for (int j = 0; j < 16; j++) { float sv = (i==j) ? 0.f : S[p*256+i*16+j];
                g_Aph[p*256+i*16+j] = sv/den*gi; }
        }
    }
}

// ---------------- weight packs: WhhH fp16 + cell-weight mma-fragment prepack ----------------
__global__ void k_trans(const float* __restrict__ Whh,
                        const float* __restrict__ cWih, const float* __restrict__ cWhh)
{
    int i = blockIdx.x*256 + threadIdx.x;
    const int T1 = 16*384*128;
    const int PP = 24*17*32;
    if (i < T1) {
        g_WhhH[i] = __float2half(Whh[i]);   // [n][g][k] direct
    } else if (i < T1 + PP) {
        int idx = i - T1;
        int lane = idx & 31;
        int kc = (idx >> 5) % 17;
        int gt = idx / (17*32);
        int lr = lane >> 2, lk = (lane & 3)*2;
        int k0 = kc*16;
        int r0 = gt*16 + lr, r1 = r0 + 8;
        __half vals[8];
        #pragma unroll
        for (int q = 0; q < 8; q++) {
            int row = (q == 2 || q == 3 || q == 6 || q == 7) ? r1 : r0;
            int kk  = k0 + ((q >= 4) ? 8 : 0) + lk + (q & 1);
            float wv = (kk < 144) ? cWih[row*144 + kk] : cWhh[row*128 + (kk - 144)];
            vals[q] = __float2half(wv);
        }
        *(int4*)(g_cWpack + (size_t)idx*8) = *(int4*)vals;
    }
}

// ---------------- K2: GRU scan, Whh@h via HMMA, fused Gx + LN, writes Hc fp16 ----------------
#define K2_SMEM_BYTES (22848*4 + (384*136 + 8*136)*2)
__global__ void __launch_bounds__(384) k2_gru(const float* __restrict__ X,
                                              const float* __restrict__ Wih,
                                              const float* __restrict__ bih,
                                              const float* __restrict__ bhh,
                                              const float* __restrict__ lng,
                                              const float* __restrict__ lnb)
{
    extern __shared__ float sm[];
    float* h32   = sm;
    float* sA    = sm + 1024;
    float* sB    = sm + 2048;
    float* sXn   = sm + 3072;
    float* sHn   = sm + 4096;
    float* ghS   = sm + 5120;
    float* Wih_s = sm + 8192;
    float* Xs    = sm + 14336;
    float* lg    = sm + 22528;
    float* lb    = sm + 22656;
    float* red1  = sm + 22784;
    float* red2  = sm + 22816;
    __half* WhhS = (__half*)(sm + 22848);
    __half* h16  = WhhS + 384*136;

    int g = threadIdx.x;
    int n = blockIdx.x >> 3, bg = blockIdx.x & 7;
    if (g < 128) { lg[g] = lng[g]; lb[g] = lnb[g]; }
    for (int i = g; i < 1024; i += 384) h32[i] = 0.f;
    for (int i = g; i < 8*136; i += 384) h16[i] = __float2half(0.f);
    for (int i = g; i < 6144; i += 384) { int g2 = i >> 4, c = i & 15;
        Wih_s[c*384 + g2] = Wih[n*6144 + i]; }
    for (int i = g; i < 384*16; i += 384) {
        int r = i >> 4, c8 = i & 15;
        *(int4*)(WhhS + r*136 + c8*8) = *(const int4*)(g_WhhH + n*49152 + r*128 + c8*8);
    }
    float bhh_g = bhh[n*384 + g];
    float bih_g = bih[n*384 + g];
    unsigned xbase = (unsigned)__cvta_generic_to_shared(Xs);
    unsigned long long bih2 = pack2(bih_g);
    int w = g >> 5, l = g & 31;
    int lr = l >> 2, lk = (l & 3)*2;
    const __half* a0base = WhhS + (w*32 + lr)*136 + lk;
    const __half* a1base = a0base + 16*136;
    const __half* bbase  = h16 + lr*136 + lk;
    __syncthreads();

    for (int t = 0; t < 256; t++) {
        int tc = t & 63;
        if (tc == 0) {
            __syncthreads();
            for (int i = g; i < 8192; i += 384) {
                int b = i >> 10, r = i & 1023, c = r >> 6, tcc = r & 63;
                Xs[c*512 + tcc*8 + b] = X[(size_t)((bg*8 + b)*16 + n)*4096 + c*256 + t + tcc];
            }
            __syncthreads();
        }
        unsigned long long g01 = bih2, g23 = bih2, g45 = bih2, g67 = bih2;
        #pragma unroll
        for (int c = 0; c < 16; c++) {
            unsigned long long w2 = pack2(Wih_s[c*384 + g]);
            unsigned long long x01, x23, x45, x67;
            unsigned xaddr = xbase + (unsigned)(c*512 + tc*8) * 4u;
            lds_v2u64(xaddr, x01, x23);
            lds_v2u64(xaddr + 16u, x45, x67);
            fma2(g01, w2, x01); fma2(g23, w2, x23);
            fma2(g45, w2, x45); fma2(g67, w2, x67);
        }
        float gx[8];
        unpack2(g01, gx[0], gx[1]); unpack2(g23, gx[2], gx[3]);
        unpack2(g45, gx[4], gx[5]); unpack2(g67, gx[6], gx[7]);
        {
            float c0[4], c1[4];
            #pragma unroll
            for (int q = 0; q < 4; q++) { c0[q] = 0.f; c1[q] = 0.f; }
            #pragma unroll
            for (int kc = 0; kc < 8; kc++) {
                int k0 = kc*16;
                uint32_t b2[2], a[4];
                b2[0] = *(const uint32_t*)(bbase + k0);
                b2[1] = *(const uint32_t*)(bbase + k0 + 8);
                a[0] = *(const uint32_t*)(a0base + k0);
                a[1] = *(const uint32_t*)(a0base + 8*136 + k0);
                a[2] = *(const uint32_t*)(a0base + k0 + 8);
                a[3] = *(const uint32_t*)(a0base + 8*136 + k0 + 8);
                mma16816(c0, a, b2);
                a[0] = *(const uint32_t*)(a1base + k0);
                a[1] = *(const uint32_t*)(a1base + 8*136 + k0);
                a[2] = *(const uint32_t*)(a1base + k0 + 8);
                a[3] = *(const uint32_t*)(a1base + 8*136 + k0 + 8);
                mma16816(c1, a, b2);
            }
            int r0 = w*32 + lr;
            *(float2*)(ghS + r0*8 + lk)      = make_float2(c0[0], c0[1]);
            *(float2*)(ghS + (r0+8)*8 + lk)  = make_float2(c0[2], c0[3]);
            *(float2*)(ghS + (r0+16)*8 + lk) = make_float2(c1[0], c1[1]);
            *(float2*)(ghS + (r0+24)*8 + lk) = make_float2(c1[2], c1[3]);
        }
        __syncthreads();
        if (g < 128) {
            #pragma unroll
            for (int b = 0; b < 8; b++) sA[g*8 + b] = gx[b] + ghS[g*8 + b] + bhh_g;
        } else if (g < 256) {
            #pragma unroll
            for (int b = 0; b < 8; b++) sB[(g-128)*8 + b] = gx[b] + ghS[g*8 + b] + bhh_g;
        } else {
            #pragma unroll
            for (int b = 0; b < 8; b++) { sXn[(g-256)*8 + b] = gx[b]; sHn[(g-256)*8 + b] = ghS[g*8 + b] + bhh_g; }
        }
        __syncthreads();
        float hnew[8];
        if (g < 128) {
            float s1[8], s2[8];
            #pragma unroll
            for (int b = 0; b < 8; b++) {
                float r  = sigm(sA[g*8 + b]);
                float z  = sigm(sB[g*8 + b]);
                float nn = tanhf(sXn[g*8 + b] + r*sHn[g*8 + b]);
                float hv = (1.f - z)*nn + z*h32[g*8 + b];
                hnew[b] = hv; h32[g*8 + b] = hv;
                h16[b*136 + g] = __float2half(hv);
                s1[b] = hv; s2[b] = hv*hv;
            }
            #pragma unroll
            for (int off = 16; off > 0; off >>= 1) {
                #pragma unroll
                for (int b = 0; b < 8; b++) {
                    s1[b] += __shfl_down_sync(0xffffffffu, s1[b], off);
                    s2[b] += __shfl_down_sync(0xffffffffu, s2[b], off);
                }
            }
            if ((g & 31) == 0) { int wq = g >> 5;
                #pragma unroll
                for (int b = 0; b < 8; b++) { red1[wq*8 + b] = s1[b]; red2[wq*8 + b] = s2[b]; }
            }
        }
        __syncthreads();
        if (g < 128) {
            #pragma unroll
            for (int b = 0; b < 8; b++) {
                float mean = (red1[b] + red1[8+b] + red1[16+b] + red1[24+b]) * 0.0078125f;
                float msq  = (red2[b] + red2[8+b] + red2[16+b] + red2[24+b]) * 0.0078125f;
                float var  = msq - mean*mean;
                float rstd = rsqrtf(var + 1e-5f);
                int bm = (bg*8 + b)*16 + n;
                g_Hc[((size_t)bm*256 + t)*144 + g] = __float2half((hnew[b] - mean)*rstd*lg[g] + lb[g]);
            }
        } else if (g < 136) {
            float uv = g_utab[t*8 + (g - 128)];
            #pragma unroll
            for (int b = 0; b < 8; b++) {
                int bm = (bg*8 + b)*16 + n;
                g_Hc[((size_t)bm*256 + t)*144 + g] = __float2half(uv);
            }
        } else if (g < 144) {
            #pragma unroll
            for (int b = 0; b < 8; b++) {
                int bm = (bg*8 + b)*16 + n;
                g_Hc[((size_t)bm*256 + t)*144 + g] = __float2half(0.f);
            }
        }
        __syncthreads();
    }
}

// ---------------- K3: P = Hc @ Wcat^T via HMMA ----------------
__global__ void __launch_bounds__(256) k3_hgemm()
{
    extern __shared__ __half smh[];
    const int PITCH = 168;
    __half* As = smh;
    __half* Bs = smh + 128*PITCH;
    int tid = threadIdx.x;
    size_t row0 = (size_t)blockIdx.x * 128;
    int col0 = blockIdx.y * 128;
    for (int i = tid; i < 128*18; i += 256) {
        int r = i / 18, c = i % 18;
        *(int4*)(As + r*PITCH + c*8) = *(const int4*)(g_Hc + (row0 + r)*144 + c*8);
    }
    for (int i = tid; i < 128*18; i += 256) {
        int r = i / 18, c = i % 18;
        *(int4*)(Bs + r*PITCH + c*8) = *(const int4*)(g_WcatH + (size_t)(col0 + r)*144 + c*8);
    }
    __syncthreads();
    int w = tid >> 5, l = tid & 31;
    int wm = w & 1, wn = w >> 1;
    int lr = l >> 2, lk = (l & 3)*2;
    float c[4][4][4];
    #pragma unroll
    for (int mi = 0; mi < 4; mi++)
        #pragma unroll
        for (int ni = 0; ni < 4; ni++)
            #pragma unroll
            for (int q = 0; q < 4; q++) c[mi][ni][q] = 0.f;
    #pragma unroll
    for (int kc = 0; kc < 9; kc++) {
        int k0 = kc*16;
        uint32_t a[4][4], b[4][2];
        #pragma unroll
        for (int mi = 0; mi < 4; mi++) {
            const __half* ap = As + (wm*64 + mi*16 + lr)*PITCH + k0 + lk;
            a[mi][0] = *(const uint32_t*)(ap);
            a[mi][1] = *(const uint32_t*)(ap + 8*PITCH);
            a[mi][2] = *(const uint32_t*)(ap + 8);
            a[mi][3] = *(const uint32_t*)(ap + 8*PITCH + 8);
        }
        #pragma unroll
        for (int ni = 0; ni < 4; ni++) {
            const __half* bp = Bs + (wn*32 + ni*8 + lr)*PITCH + k0 + lk;
            b[ni][0] = *(const uint32_t*)(bp);
            b[ni][1] = *(const uint32_t*)(bp + 8);
        }
        #pragma unroll
        for (int mi = 0; mi < 4; mi++)
            #pragma unroll
            for (int ni = 0; ni < 4; ni++)
                mma16816(c[mi][ni], a[mi], b[ni]);
    }
    #pragma unroll
    for (int mi = 0; mi < 4; mi++) {
        size_t ra = row0 + wm*64 + mi*16 + lr;
        #pragma unroll
        for (int ni = 0; ni < 4; ni++) {
            int cc = col0 + wn*32 + ni*8 + lk;
            *(__half2*)(g_P + ra*256 + cc)     = __floats2half2_rn(c[mi][ni][0], c[mi][ni][1]);
            *(__half2*)(g_P + (ra+8)*256 + cc) = __floats2half2_rn(c[mi][ni][2], c[mi][ni][3]);
        }
    }
}

// ---------------- K4: graph mix + self + leaky -> Z (fp16 IO, scalar) ----------------
__global__ void __launch_bounds__(256) k4_mix(const int* __restrict__ phases)
{
    __shared__ float Am[256], sP[2048];
    int tid = threadIdx.x; int b = blockIdx.y; int t0 = blockIdx.x*8;
    Am[tid] = g_Aph[phases[b]*256 + tid];
    for (int tc = 0; tc < 8; tc++) {
        int t = t0 + tc;
        __syncthreads();
        for (int idx = tid; idx < 2048; idx += 256) { int j = idx >> 7, d = idx & 127;
            sP[idx] = __half2float(g_P[((size_t)(b*16 + j)*256 + t)*256 + d]); }
        __syncthreads();
        for (int idx = tid; idx < 2048; idx += 256) {
            int i = idx >> 7, d = idx & 127;
            size_t row = (size_t)(b*16 + i)*256 + t;
            float accv = __half2float(g_P[row*256 + 128 + d]);
            #pragma unroll
            for (int j = 0; j < 16; j++) accv = fmaf(Am[i*16 + j], sP[j*128 + d], accv);
            g_Z[row*128 + d] = __float2half((accv >= 0.f) ? accv : 0.1f*accv);
        }
    }
}

// ---------------- K5: K|V = Z @ Wkv^T via HMMA; K fp16 [m][d][t], V fp16 [m][t][d] ----------------
__global__ void __launch_bounds__(256) k5_hgemm()
{
    extern __shared__ __half smh[];
    const int PITCH = 136;
    __half* As = smh;
    __half* Bs = smh + 128*PITCH;
    int tid = threadIdx.x;
    size_t row0 = (size_t)blockIdx.x * 128;
    int col0 = blockIdx.y * 128;
    for (int i = tid; i < 128*16; i += 256) {
        int r = i >> 4, c = i & 15;
        *(int4*)(As + r*PITCH + c*8) = *(const int4*)(g_Z + (row0 + r)*128 + c*8);
    }
    for (int i = tid; i < 128*16; i += 256) {
        int r = i >> 4, c = i & 15;
        *(int4*)(Bs + r*PITCH + c*8) = *(const int4*)(g_WkvH + (size_t)(col0 + r)*128 + c*8);
    }
    __syncthreads();
    int w = tid >> 5, l = tid & 31;
    int wm = w & 1, wn = w >> 1;
    int lr = l >> 2, lk = (l & 3)*2;
    float c[4][4][4];
    #pragma unroll
    for (int mi = 0; mi < 4; mi++)
        #pragma unroll
        for (int ni = 0; ni < 4; ni++)
            #pragma unroll
            for (int q = 0; q < 4; q++) c[mi][ni][q] = 0.f;
    #pragma unroll
    for (int kc = 0; kc < 8; kc++) {
        int k0 = kc*16;
        uint32_t a[4][4], b[4][2];
        #pragma unroll
        for (int mi = 0; mi < 4; mi++) {
            const __half* ap = As + (wm*64 + mi*16 + lr)*PITCH + k0 + lk;
            a[mi][0] = *(const uint32_t*)(ap);
            a[mi][1] = *(const uint32_t*)(ap + 8*PITCH);
            a[mi][2] = *(const uint32_t*)(ap + 8);
            a[mi][3] = *(const uint32_t*)(ap + 8*PITCH + 8);
        }
        #pragma unroll
        for (int ni = 0; ni < 4; ni++) {
            const __half* bp = Bs + (wn*32 + ni*8 + lr)*PITCH + k0 + lk;
            b[ni][0] = *(const uint32_t*)(bp);
            b[ni][1] = *(const uint32_t*)(bp + 8);
        }
        #pragma unroll
        for (int mi = 0; mi < 4; mi++)
            #pragma unroll
            for (int ni = 0; ni < 4; ni++)
                mma16816(c[mi][ni], a[mi], b[ni]);
    }
    #pragma unroll
    for (int mi = 0; mi < 4; mi++) {
        size_t ra = row0 + wm*64 + mi*16 + lr;
        size_t rb = ra + 8;
        int ma = (int)(ra >> 8), ta = (int)(ra & 255);
        int tb2 = (int)(rb & 255);
        #pragma unroll
        for (int ni = 0; ni < 4; ni++) {
            int cc = wn*32 + ni*8 + lk;
            if (blockIdx.y == 0) {
                __half* kb = g_K + (size_t)ma*32768;
                kb[(size_t)cc*256 + ta]     = __float2half(c[mi][ni][0]);
                kb[(size_t)(cc+1)*256 + ta] = __float2half(c[mi][ni][1]);
                kb[(size_t)cc*256 + tb2]     = __float2half(c[mi][ni][2]);
                kb[(size_t)(cc+1)*256 + tb2] = __float2half(c[mi][ni][3]);
            } else {
                *(__half2*)(g_V + ra*128 + cc) = __floats2half2_rn(c[mi][ni][0], c[mi][ni][1]);
                *(__half2*)(g_V + rb*128 + cc) = __floats2half2_rn(c[mi][ni][2], c[mi][ni][3]);
            }
        }
    }
}

// ---------------- K6: decode init ----------------
__global__ void k6_init()
{
    int i = blockIdx.x*256 + threadIdx.x;
    if (i < 1024*128) { int m = i >> 7, d = i & 127;
        g_h[i] = __half2float(g_Z[((size_t)m*256 + 255)*128 + d]); }
    if (i < 1024*16) { g_yA[i] = 0.f; g_yB[i] = 0.f; }
}

// ---------------- D-S1: y-mix + attention (half2) -> g_ctx, g_ymix ----------------
__global__ void __launch_bounds__(256) d_s1(const int* __restrict__ phases, int step)
{
    __shared__ float ys[256], h_s[128], sc[256], scf[256], arow[16], wred[8], cpart[512];
    int tid = threadIdx.x; int m = blockIdx.x; int b = m >> 4, n = m & 15;
    const float* y_in = (step & 1) ? g_yB : g_yA;
    ys[tid] = y_in[b*256 + tid];
    if (tid < 16) arow[tid] = g_Aph[phases[b]*256 + n*16 + tid];
    if (tid < 128) h_s[tid] = g_h[m*128 + tid];
    __syncthreads();
    if (tid < 16) {
        float a = 0.f;
        #pragma unroll
        for (int j = 0; j < 16; j++) a = fmaf(arow[j], ys[j*16 + tid], a);
        g_ymix[m*16 + tid] = ys[n*16 + tid] + 0.3f*a;
    }
    // scores: tid<128 each computes two t's (2*tid, 2*tid+1) with half2 loads
    if (tid < 128) {
        const __half* kp = g_K + (size_t)m*32768 + 2*tid;
        float s0 = 0.f, s1 = 0.f;
        #pragma unroll 8
        for (int d = 0; d < 128; d++) {
            __half2 kk = *(const __half2*)(kp + (size_t)d*256);
            float2 f = __half22float2(kk);
            float hv = h_s[d];
            s0 = fmaf(f.x, hv, s0);
            s1 = fmaf(f.y, hv, s1);
        }
        float scale = g_scale[0];
        scf[2*tid]     = s0 * scale;
        scf[2*tid + 1] = s1 * scale;
    }
    __syncthreads();
    float s = scf[tid];
    int lane = tid & 31, wid = tid >> 5;
    float wm = s;
    #pragma unroll
    for (int o = 16; o > 0; o >>= 1) wm = fmaxf(wm, __shfl_xor_sync(0xffffffffu, wm, o));
    if (lane == 0) wred[wid] = wm;
    __syncthreads();
    float mx = wred[0];
    #pragma unroll
    for (int w = 1; w < 8; w++) mx = fmaxf(mx, wred[w]);
    float e = expf(s - mx);
    float wsum = e;
    #pragma unroll
    for (int o = 16; o > 0; o >>= 1) wsum += __shfl_xor_sync(0xffffffffu, wsum, o);
    __syncthreads();
    if (lane == 0) wred[wid] = wsum;
    __syncthreads();
    float tot = 0.f;
    #pragma unroll
    for (int w = 0; w < 8; w++) tot += wred[w];
    sc[tid] = e * (1.0f / tot);
    __syncthreads();
    // ctx: thread = (t-quarter qh, d-pair p); 64 iterations of half2
    {
        int qh = tid >> 6, p = tid & 63;
        const __half* vbase = g_V + (size_t)m*32768 + (size_t)(qh*64)*128 + p*2;
        float a0 = 0.f, a1 = 0.f;
        #pragma unroll 8
        for (int tt = 0; tt < 64; tt++) {
            __half2 vv = *(const __half2*)(vbase + (size_t)tt*128);
            float2 f = __half22float2(vv);
            float svc = sc[qh*64 + tt];
            a0 = fmaf(svc, f.x, a0);
            a1 = fmaf(svc, f.y, a1);
        }
        cpart[qh*128 + p*2]     = a0;
        cpart[qh*128 + p*2 + 1] = a1;
    }
    __syncthreads();
    if (tid < 128)
        g_ctx[m*128 + tid] = cpart[tid] + cpart[128 + tid] + cpart[256 + tid] + cpart[384 + tid];
}

// ---------------- D-S2: GRU cell via HMMA + readout (8 m per block) ----------------
__global__ void __launch_bounds__(384) d_s2(const float* __restrict__ X,
                                            const float* __restrict__ cbih,
                                            const float* __restrict__ cbhh,
                                            const float* __restrict__ readW,
                                            const float* __restrict__ readb,
                                            float* __restrict__ out, int step)
{
    __shared__ float gxS[384*8], ghS[384*8], h32S[128*8], hn[128*8], ymixS[16*8];
    __shared__ __half in16[8*280];
    int tid = threadIdx.x; int m0 = blockIdx.x * 8;
    float* y_out = (step & 1) ? g_yA : g_yB;

    for (int i = tid; i < 8*272; i += 384) {
        int mm = i / 272, k = i - mm*272;
        float v = (k < 128) ? g_ctx[(m0 + mm)*128 + k]
                : (k < 144) ? g_ymix[(m0 + mm)*16 + (k - 128)]
                :             g_h[(m0 + mm)*128 + (k - 144)];
        in16[mm*280 + k] = __float2half(v);
    }
    for (int i = tid; i < 1024; i += 384) { int mm = i & 7, k = i >> 3;
        h32S[i] = g_h[(m0 + mm)*128 + k]; }
    for (int i = tid; i < 128; i += 384) { int mm = i & 7, c = i >> 3;
        ymixS[i] = g_ymix[(m0 + mm)*16 + c]; }
    __syncthreads();

    int w = tid >> 5, l = tid & 31;
    int lr = l >> 2, lk = (l & 3)*2;
    const __half* bbase = in16 + lr*280 + lk;
    #pragma unroll
    for (int mt = 0; mt < 2; mt++) {
        int gt = w*2 + mt;
        float cgx[4] = {0.f, 0.f, 0.f, 0.f};
        float cgh[4] = {0.f, 0.f, 0.f, 0.f};
        const __half* wp = g_cWpack + ((size_t)gt*17*32 + l)*8;
        #pragma unroll
        for (int kc = 0; kc < 17; kc++) {
            int4 av = *(const int4*)(wp + (size_t)kc*32*8);
            const uint32_t* a = (const uint32_t*)&av;
            int k0 = kc*16;
            uint32_t b2[2];
            b2[0] = *(const uint32_t*)(bbase + k0);
            b2[1] = *(const uint32_t*)(bbase + k0 + 8);
            if (kc < 9) mma16816(cgx, a, b2);
            else        mma16816(cgh, a, b2);
        }
        int r0 = gt*16 + lr;
        *(float2*)(gxS + r0*8 + lk)     = make_float2(cgx[0], cgx[1]);
        *(float2*)(gxS + (r0+8)*8 + lk) = make_float2(cgx[2], cgx[3]);
        *(float2*)(ghS + r0*8 + lk)     = make_float2(cgh[0], cgh[1]);
        *(float2*)(ghS + (r0+8)*8 + lk) = make_float2(cgh[2], cgh[3]);
    }
    __syncthreads();
    int g = tid;
    if (g < 128) {
        float b_r = cbih[g] + cbhh[g];
        float b_z = cbih[128 + g] + cbhh[128 + g];
        float b_ni = cbih[256 + g], b_nh = cbhh[256 + g];
        #pragma unroll
        for (int mm = 0; mm < 8; mm++) {
            float r  = sigm(gxS[g*8 + mm] + ghS[g*8 + mm] + b_r);
            float z  = sigm(gxS[(128+g)*8 + mm] + ghS[(128+g)*8 + mm] + b_z);
            float nn = tanhf(gxS[(256+g)*8 + mm] + b_ni + r*(ghS[(256+g)*8 + mm] + b_nh));
            float hv = (1.f - z)*nn + z*h32S[g*8 + mm];
            g_h[(m0 + mm)*128 + g] = hv;
            hn[g*8 + mm] = hv;
        }
    }
    __syncthreads();
    if (g < 128) {
        int c = g >> 3, r8 = g & 7;
        float a[8];
        #pragma unroll
        for (int mm = 0; mm < 8; mm++) a[mm] = 0.f;
        const float* rw = readW + c*128 + r8*16;
        #pragma unroll
        for (int i = 0; i < 16; i++) {
            float wv = rw[i];
            const float* hp = hn + (r8*16 + i)*8;
            #pragma unroll
            for (int mm = 0; mm < 8; mm++) a[mm] = fmaf(wv, hp[mm], a[mm]);
        }
        #pragma unroll
        for (int mm = 0; mm < 8; mm++) {
            a[mm] += __shfl_down_sync(0xffffffffu, a[mm], 4, 8);
            a[mm] += __shfl_down_sync(0xffffffffu, a[mm], 2, 8);
            a[mm] += __shfl_down_sync(0xffffffffu, a[mm], 1, 8);
        }
        if (r8 == 0) {
            float rb = readb[c];
            #pragma unroll
            for (int mm = 0; mm < 8; mm++) {
                int mc = (m0 + mm)*16 + c;
                float yt = a[mm] + rb + ymixS[c*8 + mm];
                y_out[mc] = yt;
                float vv = X[(size_t)mc*256 + 255] + yt;
                out[mc*32 + step] = vv;
                if (step == 0) out[524288 + mc] = vv;
            }
        }
    }
}

// ---------------- host launch ----------------
extern "C" void kernel_launch(void* const* d_in, const int* in_sizes, int n_in,
                              void* d_out, int out_size)
{
    const float* X      = (const float*)d_in[0];
    const int*   phases = (const int*)  d_in[1];
    const float* gWih   = (const float*)d_in[2];
    const float* gWhh   = (const float*)d_in[3];
    const float* gbih   = (const float*)d_in[4];
    const float* gbhh   = (const float*)d_in[5];
    const float* lng    = (const float*)d_in[6];
    const float* lnb    = (const float*)d_in[7];
    const float* tW     = (const float*)d_in[8];
    const float* tb     = (const float*)d_in[9];
    const float* S      = (const float*)d_in[10];
    const float* G      = (const float*)d_in[11];
    const float* Wself  = (const float*)d_in[12];
    const float* Wneigh = (const float*)d_in[13];
    const float* cWih   = (const float*)d_in[14];
    const float* cWhh   = (const float*)d_in[15];
    const float* cbih   = (const float*)d_in[16];
    const float* cbhh   = (const float*)d_in[17];
    const float* readW  = (const float*)d_in[18];
    const float* readb  = (const float*)d_in[19];
    const float* Wk     = (const float*)d_in[20];
    const float* Wv     = (const float*)d_in[21];
    const float* ltau   = (const float*)d_in[22];
    float* out = (float*)d_out;

    const int k2_smem = K2_SMEM_BYTES;
    const int k3_smem = 2 * 128 * 168 * (int)sizeof(__half);  // 86016
    const int k5_smem = 2 * 128 * 136 * (int)sizeof(__half);  // 69632
    cudaFuncSetAttribute(k2_gru, cudaFuncAttributeMaxDynamicSharedMemorySize, k2_smem);
    cudaFuncSetAttribute(k3_hgemm, cudaFuncAttributeMaxDynamicSharedMemorySize, k3_smem);
    cudaFuncSetAttribute(k5_hgemm, cudaFuncAttributeMaxDynamicSharedMemorySize, k5_smem);

    k0_prep<<<1, 256>>>(Wneigh, Wself, Wk, Wv, S, G, tW, tb, ltau);
    {
        int total = 16*384*128 + 24*17*32;
        k_trans<<<(total + 255)/256, 256>>>(gWhh, cWih, cWhh);
    }
    k2_gru<<<128, 384, k2_smem>>>(X, gWih, gbih, gbhh, lng, lnb);
    k3_hgemm<<<dim3(2048, 2), 256, k3_smem>>>();
    k4_mix<<<dim3(32, 64), 256>>>(phases);
    k5_hgemm<<<dim3(2048, 2), 256, k5_smem>>>();
    k6_init<<<512, 256>>>();
    for (int s = 0; s < 32; s++) {
        d_s1<<<1024, 256>>>(phases, s);
        d_s2<<<128, 384>>>(X, cbih, cbhh, readW, readb, out, s);
    }
    (void)in_sizes; (void)n_in; (void)out_size;
}

// round 14
// speedup vs baseline: 2.0843x; 1.0446x over previous
#include <cuda_runtime.h>
#include <cuda_fp16.h>
#include <cstdint>

// ---------------- problem constants ----------------
// B=64 N=16 C=16 T=256 DH=128 DT=8 DP=128 TOUT=32 P=4 DIN=136

// ---------------- scratch (static device arrays; no allocation) ----------------
__device__ __half g_Hc [64u*16u*256u*144u];  // [row][144] fp16, cols 136..143 = 0
__device__ __half g_P  [64u*16u*256u*256u];  // [row][0:128]=Hc*Wn^T, [128:256]=Hc*Wself^T
__device__ __half g_Z  [64u*16u*256u*128u];  // [row][128] fp16
__device__ __half g_K [1024u*128u*256u];     // [m][d][t]  fp16 (transposed for decoder)
__device__ __half g_V [1024u*256u*128u];     // [m][t][d]  fp16
__device__ __half g_WfullH[16*384*144];      // [n][g][k]: k0..15=Wih, k16..143=Whh (fp16)
__device__ __half g_WcatH[256*144];          // rows 0..127 = Wn/sigma, 128..255 = W_self
__device__ __half g_WkvH [256*128];          // rows 0..127 = Wk, 128..255 = Wv
__device__ __half g_cWpack[24*17*32*8];      // cell weights, mma-fragment order
__device__ float g_Aph  [4*16*16];
__device__ float g_utab [256*8];
__device__ float g_h   [1024*128];
__device__ float g_yA  [1024*16];
__device__ float g_yB  [1024*16];
__device__ float g_ctx [1024*128];
__device__ float g_ymix[1024*16];
__device__ float g_scale[1];

__device__ __forceinline__ float sigm(float x){ return 1.0f/(1.0f+expf(-x)); }

__device__ __forceinline__ void mma16816(float* c, const uint32_t* a, const uint32_t* b) {
    asm volatile("mma.sync.aligned.m16n8k16.row.col.f32.f16.f16.f32 "
        "{%0,%1,%2,%3}, {%4,%5,%6,%7}, {%8,%9}, {%0,%1,%2,%3};"
        : "+f"(c[0]), "+f"(c[1]), "+f"(c[2]), "+f"(c[3])
        : "r"(a[0]), "r"(a[1]), "r"(a[2]), "r"(a[3]), "r"(b[0]), "r"(b[1]));
}

// ---------------- K0: spectral norm, phase graphs, u table, weight packs ----------------
__global__ void __launch_bounds__(256) k0_prep(
    const float* __restrict__ Wneigh, const float* __restrict__ Wself,
    const float* __restrict__ Wk, const float* __restrict__ Wv,
    const float* __restrict__ S, const float* __restrict__ G,
    const float* __restrict__ tW, const float* __restrict__ tb,
    const float* __restrict__ ltau)
{
    __shared__ float u[128], v[136], red[256], sig;
    int tid = threadIdx.x;
    if (tid < 128) u[tid] = 1.0f / sqrtf(128.0f);
    __syncthreads();
    for (int it = 0; it < 15; it++) {
        float vv = 0.f;
        if (tid < 136) { float s = 0.f; for (int i = 0; i < 128; i++) s += Wneigh[i*136+tid]*u[i]; vv = s; }
        red[tid] = (tid < 136) ? vv*vv : 0.f; __syncthreads();
        for (int o = 128; o > 0; o >>= 1) { if (tid < o) red[tid] += red[tid+o]; __syncthreads(); }
        float nv = sqrtf(red[0]); __syncthreads();
        if (tid < 136) v[tid] = vv / nv;
        __syncthreads();
        float uu = 0.f;
        if (tid < 128) { float s = 0.f; for (int j = 0; j < 136; j++) s += Wneigh[tid*136+j]*v[j]; uu = s; }
        red[tid] = (tid < 128) ? uu*uu : 0.f; __syncthreads();
        for (int o = 128; o > 0; o >>= 1) { if (tid < o) red[tid] += red[tid+o]; __syncthreads(); }
        float nu = sqrtf(red[0]); __syncthreads();
        if (tid < 128) u[tid] = uu / nu;
        __syncthreads();
    }
    {
        float p = 0.f;
        if (tid < 128) { float s = 0.f; for (int j = 0; j < 136; j++) s += Wneigh[tid*136+j]*v[j]; p = u[tid]*s; }
        red[tid] = p; __syncthreads();
        for (int o = 128; o > 0; o >>= 1) { if (tid < o) red[tid] += red[tid+o]; __syncthreads(); }
        if (tid == 0) sig = red[0];
        __syncthreads();
    }
    float inv = 1.0f / sig;
    for (int i = tid; i < 128*144; i += 256) {
        int r = i / 144, cidx = i % 144;
        float wn_ = (cidx < 136) ? Wneigh[r*136 + cidx]*inv : 0.f;
        float ws_ = (cidx < 136) ? Wself[r*136 + cidx] : 0.f;
        g_WcatH[i] = __float2half(wn_);
        g_WcatH[128*144 + i] = __float2half(ws_);
    }
    for (int i = tid; i < 128*128; i += 256) {
        g_WkvH[i] = __float2half(Wk[i]);
        g_WkvH[16384 + i] = __float2half(Wv[i]);
    }
    for (int i = tid; i < 256*8;   i += 256) { int t = i >> 3, j = i & 7;
        g_utab[i] = tanhf(((float)t * (1.0f/255.0f)) * tW[j] + tb[j]); }
    if (tid == 0) g_scale[0] = expf(ltau[0]);
    if (tid < 4) {
        int p = tid; float gg[16]; float gs = 0.f;
        for (int i = 0; i < 16; i++) { float x = G[p*16+i]; float sp = log1pf(expf(x)) + 1e-6f; gg[i] = sp; gs += sp; }
        float gn = 16.0f / fmaxf(gs, 1e-6f);
        for (int i = 0; i < 16; i++) {
            float den = 0.f;
            for (int j = 0; j < 16; j++) { float sv = (i==j) ? 0.f : S[p*256+i*16+j]; den += fabsf(sv); }
            den = fmaxf(den, 1e-6f);
            float gi = gg[i]*gn;
            for (int j = 0; j < 16; j++) { float sv = (i==j) ? 0.f : S[p*256+i*16+j];
                g_Aph[p*256+i*16+j] = sv/den*gi; }
        }
    }
}

// ---------------- weight packs ----------------
__global__ void k_trans(const float* __restrict__ Wih, const float* __restrict__ Whh,
                        const float* __restrict__ cWih, const float* __restrict__ cWhh)
{
    int i = blockIdx.x*256 + threadIdx.x;
    const int T1 = 16*384*144;
    const int PP = 24*17*32;
    if (i < T1) {
        int n = i / 55296, r = i % 55296, gg = r / 144, k = r % 144;
        float v = (k < 16) ? Wih[n*6144 + gg*16 + k] : Whh[n*49152 + gg*128 + (k - 16)];
        g_WfullH[i] = __float2half(v);
    } else if (i < T1 + PP) {
        int idx = i - T1;
        int lane = idx & 31;
        int kc = (idx >> 5) % 17;
        int gt = idx / (17*32);
        int lr = lane >> 2, lk = (lane & 3)*2;
        int k0 = kc*16;
        int r0 = gt*16 + lr, r1 = r0 + 8;
        __half vals[8];
        #pragma unroll
        for (int q = 0; q < 8; q++) {
            int row = (q == 2 || q == 3 || q == 6 || q == 7) ? r1 : r0;
            int kk  = k0 + ((q >= 4) ? 8 : 0) + lk + (q & 1);
            float wv = (kk < 144) ? cWih[row*144 + kk] : cWhh[row*128 + (kk - 144)];
            vals[q] = __float2half(wv);
        }
        *(int4*)(g_cWpack + (size_t)idx*8) = *(int4*)vals;
    }
}

// ---------------- K2: GRU scan, full-gate HMMA (x+h fused operand), LN, writes Hc fp16 ----------------
// float region: h32[0,1024) ghS[1024,4096) gxS[4096,7168) Xs[7168,15360)
//               lg[15360,15488) lb[15488,15616) red1[15616,15648) red2[15648,15680)
// half region:  WS 384x152, h16 8x152  (k0..15 = x, k16..143 = h)
#define K2_SMEM_BYTES (15680*4 + (384*152 + 8*152)*2)
__global__ void __launch_bounds__(384) k2_gru(const float* __restrict__ X,
                                              const float* __restrict__ bih,
                                              const float* __restrict__ bhh,
                                              const float* __restrict__ lng,
                                              const float* __restrict__ lnb)
{
    extern __shared__ float sm[];
    float* h32  = sm;
    float* ghS  = sm + 1024;
    float* gxS  = sm + 4096;
    float* Xs   = sm + 7168;
    float* lg   = sm + 15360;
    float* lb   = sm + 15488;
    float* red1 = sm + 15616;
    float* red2 = sm + 15648;
    __half* WS  = (__half*)(sm + 15680);
    __half* h16 = WS + 384*152;

    int g = threadIdx.x;
    int n = blockIdx.x >> 3, bg = blockIdx.x & 7;
    if (g < 128) { lg[g] = lng[g]; lb[g] = lnb[g]; }
    for (int i = g; i < 1024; i += 384) h32[i] = 0.f;
    for (int i = g; i < 8*152; i += 384) h16[i] = __float2half(0.f);
    for (int i = g; i < 384*18; i += 384) {
        int r = i / 18, c8 = i % 18;
        *(int4*)(WS + r*152 + c8*8) = *(const int4*)(g_WfullH + (size_t)n*55296 + r*144 + c8*8);
    }
    float b_r = 0.f, b_z = 0.f, b_xn = 0.f, b_hn = 0.f;
    if (g < 128) {
        b_r  = bih[n*384 + g] + bhh[n*384 + g];
        b_z  = bih[n*384 + 128 + g] + bhh[n*384 + 128 + g];
        b_xn = bih[n*384 + 256 + g];
        b_hn = bhh[n*384 + 256 + g];
    }
    int w = g >> 5, l = g & 31;
    int lr = l >> 2, lk = (l & 3)*2;
    const __half* a0base = WS + (w*32 + lr)*152 + lk;
    const __half* a1base = a0base + 16*152;
    const __half* bbase  = h16 + lr*152 + lk;
    __syncthreads();

    for (int t = 0; t < 256; t++) {
        int tc = t & 63;
        if (tc == 0) {
            __syncthreads();
            for (int i = g; i < 8192; i += 384) {
                int b = i >> 10, r = i & 1023, c = r >> 6, tcc = r & 63;
                Xs[c*512 + tcc*8 + b] = X[(size_t)((bg*8 + b)*16 + n)*4096 + c*256 + t + tcc];
            }
            __syncthreads();
        }
        // stage x for this t into operand (k 0..15)
        if (g < 128) {
            int b = g & 7, c = g >> 3;
            h16[b*152 + c] = __float2half(Xs[c*512 + tc*8 + b]);
        }
        __syncthreads();
        // HMMA: gates = Wfull @ [x; h];  kc=0 -> gx (Wih*x), kc=1..8 -> gh (Whh*h)
        {
            float cx0[4] = {0,0,0,0}, cx1[4] = {0,0,0,0};
            float ch0[4] = {0,0,0,0}, ch1[4] = {0,0,0,0};
            #pragma unroll
            for (int kc = 0; kc < 9; kc++) {
                int k0 = kc*16;
                uint32_t b2[2], a[4];
                b2[0] = *(const uint32_t*)(bbase + k0);
                b2[1] = *(const uint32_t*)(bbase + k0 + 8);
                a[0] = *(const uint32_t*)(a0base + k0);
                a[1] = *(const uint32_t*)(a0base + 8*152 + k0);
                a[2] = *(const uint32_t*)(a0base + k0 + 8);
                a[3] = *(const uint32_t*)(a0base + 8*152 + k0 + 8);
                if (kc == 0) mma16816(cx0, a, b2); else mma16816(ch0, a, b2);
                a[0] = *(const uint32_t*)(a1base + k0);
                a[1] = *(const uint32_t*)(a1base + 8*152 + k0);
                a[2] = *(const uint32_t*)(a1base + k0 + 8);
                a[3] = *(const uint32_t*)(a1base + 8*152 + k0 + 8);
                if (kc == 0) mma16816(cx1, a, b2); else mma16816(ch1, a, b2);
            }
            int r0 = w*32 + lr;
            *(float2*)(gxS + r0*8 + lk)      = make_float2(cx0[0], cx0[1]);
            *(float2*)(gxS + (r0+8)*8 + lk)  = make_float2(cx0[2], cx0[3]);
            *(float2*)(gxS + (r0+16)*8 + lk) = make_float2(cx1[0], cx1[1]);
            *(float2*)(gxS + (r0+24)*8 + lk) = make_float2(cx1[2], cx1[3]);
            *(float2*)(ghS + r0*8 + lk)      = make_float2(ch0[0], ch0[1]);
            *(float2*)(ghS + (r0+8)*8 + lk)  = make_float2(ch0[2], ch0[3]);
            *(float2*)(ghS + (r0+16)*8 + lk) = make_float2(ch1[0], ch1[1]);
            *(float2*)(ghS + (r0+24)*8 + lk) = make_float2(ch1[2], ch1[3]);
        }
        __syncthreads();
        float hnew[8];
        if (g < 128) {
            float s1[8], s2[8];
            #pragma unroll
            for (int b = 0; b < 8; b++) {
                float r  = sigm(gxS[g*8 + b] + ghS[g*8 + b] + b_r);
                float z  = sigm(gxS[(128+g)*8 + b] + ghS[(128+g)*8 + b] + b_z);
                float nn = tanhf(gxS[(256+g)*8 + b] + b_xn + r*(ghS[(256+g)*8 + b] + b_hn));
                float hv = (1.f - z)*nn + z*h32[g*8 + b];
                hnew[b] = hv; h32[g*8 + b] = hv;
                h16[b*152 + 16 + g] = __float2half(hv);
                s1[b] = hv; s2[b] = hv*hv;
            }
            #pragma unroll
            for (int off = 16; off > 0; off >>= 1) {
                #pragma unroll
                for (int b = 0; b < 8; b++) {
                    s1[b] += __shfl_down_sync(0xffffffffu, s1[b], off);
                    s2[b] += __shfl_down_sync(0xffffffffu, s2[b], off);
                }
            }
            if ((g & 31) == 0) { int wq = g >> 5;
                #pragma unroll
                for (int b = 0; b < 8; b++) { red1[wq*8 + b] = s1[b]; red2[wq*8 + b] = s2[b]; }
            }
        }
        __syncthreads();
        if (g < 128) {
            #pragma unroll
            for (int b = 0; b < 8; b++) {
                float mean = (red1[b] + red1[8+b] + red1[16+b] + red1[24+b]) * 0.0078125f;
                float msq  = (red2[b] + red2[8+b] + red2[16+b] + red2[24+b]) * 0.0078125f;
                float var  = msq - mean*mean;
                float rstd = rsqrtf(var + 1e-5f);
                int bm = (bg*8 + b)*16 + n;
                g_Hc[((size_t)bm*256 + t)*144 + g] = __float2half((hnew[b] - mean)*rstd*lg[g] + lb[g]);
            }
        } else if (g < 136) {
            float uv = g_utab[t*8 + (g - 128)];
            #pragma unroll
            for (int b = 0; b < 8; b++) {
                int bm = (bg*8 + b)*16 + n;
                g_Hc[((size_t)bm*256 + t)*144 + g] = __float2half(uv);
            }
        } else if (g < 144) {
            #pragma unroll
            for (int b = 0; b < 8; b++) {
                int bm = (bg*8 + b)*16 + n;
                g_Hc[((size_t)bm*256 + t)*144 + g] = __float2half(0.f);
            }
        }
        __syncthreads();
    }
}

// ---------------- K3: P = Hc @ Wcat^T via HMMA ----------------
__global__ void __launch_bounds__(256) k3_hgemm()
{
    extern __shared__ __half smh[];
    const int PITCH = 168;
    __half* As = smh;
    __half* Bs = smh + 128*PITCH;
    int tid = threadIdx.x;
    size_t row0 = (size_t)blockIdx.x * 128;
    int col0 = blockIdx.y * 128;
    for (int i = tid; i < 128*18; i += 256) {
        int r = i / 18, c = i % 18;
        *(int4*)(As + r*PITCH + c*8) = *(const int4*)(g_Hc + (row0 + r)*144 + c*8);
    }
    for (int i = tid; i < 128*18; i += 256) {
        int r = i / 18, c = i % 18;
        *(int4*)(Bs + r*PITCH + c*8) = *(const int4*)(g_WcatH + (size_t)(col0 + r)*144 + c*8);
    }
    __syncthreads();
    int w = tid >> 5, l = tid & 31;
    int wm = w & 1, wn = w >> 1;
    int lr = l >> 2, lk = (l & 3)*2;
    float c[4][4][4];
    #pragma unroll
    for (int mi = 0; mi < 4; mi++)
        #pragma unroll
        for (int ni = 0; ni < 4; ni++)
            #pragma unroll
            for (int q = 0; q < 4; q++) c[mi][ni][q] = 0.f;
    #pragma unroll
    for (int kc = 0; kc < 9; kc++) {
        int k0 = kc*16;
        uint32_t a[4][4], b[4][2];
        #pragma unroll
        for (int mi = 0; mi < 4; mi++) {
            const __half* ap = As + (wm*64 + mi*16 + lr)*PITCH + k0 + lk;
            a[mi][0] = *(const uint32_t*)(ap);
            a[mi][1] = *(const uint32_t*)(ap + 8*PITCH);
            a[mi][2] = *(const uint32_t*)(ap + 8);
            a[mi][3] = *(const uint32_t*)(ap + 8*PITCH + 8);
        }
        #pragma unroll
        for (int ni = 0; ni < 4; ni++) {
            const __half* bp = Bs + (wn*32 + ni*8 + lr)*PITCH + k0 + lk;
            b[ni][0] = *(const uint32_t*)(bp);
            b[ni][1] = *(const uint32_t*)(bp + 8);
        }
        #pragma unroll
        for (int mi = 0; mi < 4; mi++)
            #pragma unroll
            for (int ni = 0; ni < 4; ni++)
                mma16816(c[mi][ni], a[mi], b[ni]);
    }
    #pragma unroll
    for (int mi = 0; mi < 4; mi++) {
        size_t ra = row0 + wm*64 + mi*16 + lr;
        #pragma unroll
        for (int ni = 0; ni < 4; ni++) {
            int cc = col0 + wn*32 + ni*8 + lk;
            *(__half2*)(g_P + ra*256 + cc)     = __floats2half2_rn(c[mi][ni][0], c[mi][ni][1]);
            *(__half2*)(g_P + (ra+8)*256 + cc) = __floats2half2_rn(c[mi][ni][2], c[mi][ni][3]);
        }
    }
}

// ---------------- K4: graph mix + self + leaky -> Z (fp16 IO, scalar) ----------------
__global__ void __launch_bounds__(256) k4_mix(const int* __restrict__ phases)
{
    __shared__ float Am[256], sP[2048];
    int tid = threadIdx.x; int b = blockIdx.y; int t0 = blockIdx.x*8;
    Am[tid] = g_Aph[phases[b]*256 + tid];
    for (int tc = 0; tc < 8; tc++) {
        int t = t0 + tc;
        __syncthreads();
        for (int idx = tid; idx < 2048; idx += 256) { int j = idx >> 7, d = idx & 127;
            sP[idx] = __half2float(g_P[((size_t)(b*16 + j)*256 + t)*256 + d]); }
        __syncthreads();
        for (int idx = tid; idx < 2048; idx += 256) {
            int i = idx >> 7, d = idx & 127;
            size_t row = (size_t)(b*16 + i)*256 + t;
            float accv = __half2float(g_P[row*256 + 128 + d]);
            #pragma unroll
            for (int j = 0; j < 16; j++) accv = fmaf(Am[i*16 + j], sP[j*128 + d], accv);
            g_Z[row*128 + d] = __float2half((accv >= 0.f) ? accv : 0.1f*accv);
        }
    }
}

// ---------------- K5: K|V = Z @ Wkv^T via HMMA; K fp16 [m][d][t], V fp16 [m][t][d] ----------------
__global__ void __launch_bounds__(256) k5_hgemm()
{
    extern __shared__ __half smh[];
    const int PITCH = 136;
    __half* As = smh;
    __half* Bs = smh + 128*PITCH;
    int tid = threadIdx.x;
    size_t row0 = (size_t)blockIdx.x * 128;
    int col0 = blockIdx.y * 128;
    for (int i = tid; i < 128*16; i += 256) {
        int r = i >> 4, c = i & 15;
        *(int4*)(As + r*PITCH + c*8) = *(const int4*)(g_Z + (row0 + r)*128 + c*8);
    }
    for (int i = tid; i < 128*16; i += 256) {
        int r = i >> 4, c = i & 15;
        *(int4*)(Bs + r*PITCH + c*8) = *(const int4*)(g_WkvH + (size_t)(col0 + r)*128 + c*8);
    }
    __syncthreads();
    int w = tid >> 5, l = tid & 31;
    int wm = w & 1, wn = w >> 1;
    int lr = l >> 2, lk = (l & 3)*2;
    float c[4][4][4];
    #pragma unroll
    for (int mi = 0; mi < 4; mi++)
        #pragma unroll
        for (int ni = 0; ni < 4; ni++)
            #pragma unroll
            for (int q = 0; q < 4; q++) c[mi][ni][q] = 0.f;
    #pragma unroll
    for (int kc = 0; kc < 8; kc++) {
        int k0 = kc*16;
        uint32_t a[4][4], b[4][2];
        #pragma unroll
        for (int mi = 0; mi < 4; mi++) {
            const __half* ap = As + (wm*64 + mi*16 + lr)*PITCH + k0 + lk;
            a[mi][0] = *(const uint32_t*)(ap);
            a[mi][1] = *(const uint32_t*)(ap + 8*PITCH);
            a[mi][2] = *(const uint32_t*)(ap + 8);
            a[mi][3] = *(const uint32_t*)(ap + 8*PITCH + 8);
        }
        #pragma unroll
        for (int ni = 0; ni < 4; ni++) {
            const __half* bp = Bs + (wn*32 + ni*8 + lr)*PITCH + k0 + lk;
            b[ni][0] = *(const uint32_t*)(bp);
            b[ni][1] = *(const uint32_t*)(bp + 8);
        }
        #pragma unroll
        for (int mi = 0; mi < 4; mi++)
            #pragma unroll
            for (int ni = 0; ni < 4; ni++)
                mma16816(c[mi][ni], a[mi], b[ni]);
    }
    #pragma unroll
    for (int mi = 0; mi < 4; mi++) {
        size_t ra = row0 + wm*64 + mi*16 + lr;
        size_t rb = ra + 8;
        int ma = (int)(ra >> 8), ta = (int)(ra & 255);
        int tb2 = (int)(rb & 255);
        #pragma unroll
        for (int ni = 0; ni < 4; ni++) {
            int cc = wn*32 + ni*8 + lk;
            if (blockIdx.y == 0) {
                __half* kb = g_K + (size_t)ma*32768;
                kb[(size_t)cc*256 + ta]     = __float2half(c[mi][ni][0]);
                kb[(size_t)(cc+1)*256 + ta] = __float2half(c[mi][ni][1]);
                kb[(size_t)cc*256 + tb2]     = __float2half(c[mi][ni][2]);
                kb[(size_t)(cc+1)*256 + tb2] = __float2half(c[mi][ni][3]);
            } else {
                *(__half2*)(g_V + ra*128 + cc) = __floats2half2_rn(c[mi][ni][0], c[mi][ni][1]);
                *(__half2*)(g_V + rb*128 + cc) = __floats2half2_rn(c[mi][ni][2], c[mi][ni][3]);
            }
        }
    }
}

// ---------------- K6: decode init ----------------
__global__ void k6_init()
{
    int i = blockIdx.x*256 + threadIdx.x;
    if (i < 1024*128) { int m = i >> 7, d = i & 127;
        g_h[i] = __half2float(g_Z[((size_t)m*256 + 255)*128 + d]); }
    if (i < 1024*16) { g_yA[i] = 0.f; g_yB[i] = 0.f; }
}

// ---------------- D-S1: y-mix + attention (half2) -> g_ctx, g_ymix ----------------
__global__ void __launch_bounds__(256) d_s1(const int* __restrict__ phases, int step)
{
    __shared__ float ys[256], h_s[128], sc[256], scf[256], arow[16], wred[8], cpart[512];
    int tid = threadIdx.x; int m = blockIdx.x; int b = m >> 4, n = m & 15;
    const float* y_in = (step & 1) ? g_yB : g_yA;
    ys[tid] = y_in[b*256 + tid];
    if (tid < 16) arow[tid] = g_Aph[phases[b]*256 + n*16 + tid];
    if (tid < 128) h_s[tid] = g_h[m*128 + tid];
    __syncthreads();
    if (tid < 16) {
        float a = 0.f;
        #pragma unroll
        for (int j = 0; j < 16; j++) a = fmaf(arow[j], ys[j*16 + tid], a);
        g_ymix[m*16 + tid] = ys[n*16 + tid] + 0.3f*a;
    }
    if (tid < 128) {
        const __half* kp = g_K + (size_t)m*32768 + 2*tid;
        float s0 = 0.f, s1 = 0.f;
        #pragma unroll 8
        for (int d = 0; d < 128; d++) {
            __half2 kk = *(const __half2*)(kp + (size_t)d*256);
            float2 f = __half22float2(kk);
            float hv = h_s[d];
            s0 = fmaf(f.x, hv, s0);
            s1 = fmaf(f.y, hv, s1);
        }
        float scale = g_scale[0];
        scf[2*tid]     = s0 * scale;
        scf[2*tid + 1] = s1 * scale;
    }
    __syncthreads();
    float s = scf[tid];
    int lane = tid & 31, wid = tid >> 5;
    float wm = s;
    #pragma unroll
    for (int o = 16; o > 0; o >>= 1) wm = fmaxf(wm, __shfl_xor_sync(0xffffffffu, wm, o));
    if (lane == 0) wred[wid] = wm;
    __syncthreads();
    float mx = wred[0];
    #pragma unroll
    for (int w = 1; w < 8; w++) mx = fmaxf(mx, wred[w]);
    float e = expf(s - mx);
    float wsum = e;
    #pragma unroll
    for (int o = 16; o > 0; o >>= 1) wsum += __shfl_xor_sync(0xffffffffu, wsum, o);
    __syncthreads();
    if (lane == 0) wred[wid] = wsum;
    __syncthreads();
    float tot = 0.f;
    #pragma unroll
    for (int w = 0; w < 8; w++) tot += wred[w];
    sc[tid] = e * (1.0f / tot);
    __syncthreads();
    {
        int qh = tid >> 6, p = tid & 63;
        const __half* vbase = g_V + (size_t)m*32768 + (size_t)(qh*64)*128 + p*2;
        float a0 = 0.f, a1 = 0.f;
        #pragma unroll 8
        for (int tt = 0; tt < 64; tt++) {
            __half2 vv = *(const __half2*)(vbase + (size_t)tt*128);
            float2 f = __half22float2(vv);
            float svc = sc[qh*64 + tt];
            a0 = fmaf(svc, f.x, a0);
            a1 = fmaf(svc, f.y, a1);
        }
        cpart[qh*128 + p*2]     = a0;
        cpart[qh*128 + p*2 + 1] = a1;
    }
    __syncthreads();
    if (tid < 128)
        g_ctx[m*128 + tid] = cpart[tid] + cpart[128 + tid] + cpart[256 + tid] + cpart[384 + tid];
}

// ---------------- D-S2: GRU cell via HMMA + readout (8 m per block) ----------------
__global__ void __launch_bounds__(384) d_s2(const float* __restrict__ X,
                                            const float* __restrict__ cbih,
                                            const float* __restrict__ cbhh,
                                            const float* __restrict__ readW,
                                            const float* __restrict__ readb,
                                            float* __restrict__ out, int step)
{
    __shared__ float gxS[384*8], ghS[384*8], h32S[128*8], hn[128*8], ymixS[16*8];
    __shared__ __half in16[8*280];
    int tid = threadIdx.x; int m0 = blockIdx.x * 8;
    float* y_out = (step & 1) ? g_yA : g_yB;

    for (int i = tid; i < 8*272; i += 384) {
        int mm = i / 272, k = i - mm*272;
        float v = (k < 128) ? g_ctx[(m0 + mm)*128 + k]
                : (k < 144) ? g_ymix[(m0 + mm)*16 + (k - 128)]
                :             g_h[(m0 + mm)*128 + (k - 144)];
        in16[mm*280 + k] = __float2half(v);
    }
    for (int i = tid; i < 1024; i += 384) { int mm = i & 7, k = i >> 3;
        h32S[i] = g_h[(m0 + mm)*128 + k]; }
    for (int i = tid; i < 128; i += 384) { int mm = i & 7, c = i >> 3;
        ymixS[i] = g_ymix[(m0 + mm)*16 + c]; }
    __syncthreads();

    int w = tid >> 5, l = tid & 31;
    int lr = l >> 2, lk = (l & 3)*2;
    const __half* bbase = in16 + lr*280 + lk;
    #pragma unroll
    for (int mt = 0; mt < 2; mt++) {
        int gt = w*2 + mt;
        float cgx[4] = {0.f, 0.f, 0.f, 0.f};
        float cgh[4] = {0.f, 0.f, 0.f, 0.f};
        const __half* wp = g_cWpack + ((size_t)gt*17*32 + l)*8;
        #pragma unroll
        for (int kc = 0; kc < 17; kc++) {
            int4 av = *(const int4*)(wp + (size_t)kc*32*8);
            const uint32_t* a = (const uint32_t*)&av;
            int k0 = kc*16;
            uint32_t b2[2];
            b2[0] = *(const uint32_t*)(bbase + k0);
            b2[1] = *(const uint32_t*)(bbase + k0 + 8);
            if (kc < 9) mma16816(cgx, a, b2);
            else        mma16816(cgh, a, b2);
        }
        int r0 = gt*16 + lr;
        *(float2*)(gxS + r0*8 + lk)     = make_float2(cgx[0], cgx[1]);
        *(float2*)(gxS + (r0+8)*8 + lk) = make_float2(cgx[2], cgx[3]);
        *(float2*)(ghS + r0*8 + lk)     = make_float2(cgh[0], cgh[1]);
        *(float2*)(ghS + (r0+8)*8 + lk) = make_float2(cgh[2], cgh[3]);
    }
    __syncthreads();
    int g = tid;
    if (g < 128) {
        float b_r = cbih[g] + cbhh[g];
        float b_z = cbih[128 + g] + cbhh[128 + g];
        float b_ni = cbih[256 + g], b_nh = cbhh[256 + g];
        #pragma unroll
        for (int mm = 0; mm < 8; mm++) {
            float r  = sigm(gxS[g*8 + mm] + ghS[g*8 + mm] + b_r);
            float z  = sigm(gxS[(128+g)*8 + mm] + ghS[(128+g)*8 + mm] + b_z);
            float nn = tanhf(gxS[(256+g)*8 + mm] + b_ni + r*(ghS[(256+g)*8 + mm] + b_nh));
            float hv = (1.f - z)*nn + z*h32S[g*8 + mm];
            g_h[(m0 + mm)*128 + g] = hv;
            hn[g*8 + mm] = hv;
        }
    }
    __syncthreads();
    if (g < 128) {
        int c = g >> 3, r8 = g & 7;
        float a[8];
        #pragma unroll
        for (int mm = 0; mm < 8; mm++) a[mm] = 0.f;
        const float* rw = readW + c*128 + r8*16;
        #pragma unroll
        for (int i = 0; i < 16; i++) {
            float wv = rw[i];
            const float* hp = hn + (r8*16 + i)*8;
            #pragma unroll
            for (int mm = 0; mm < 8; mm++) a[mm] = fmaf(wv, hp[mm], a[mm]);
        }
        #pragma unroll
        for (int mm = 0; mm < 8; mm++) {
            a[mm] += __shfl_down_sync(0xffffffffu, a[mm], 4, 8);
            a[mm] += __shfl_down_sync(0xffffffffu, a[mm], 2, 8);
            a[mm] += __shfl_down_sync(0xffffffffu, a[mm], 1, 8);
        }
        if (r8 == 0) {
            float rb = readb[c];
            #pragma unroll
            for (int mm = 0; mm < 8; mm++) {
                int mc = (m0 + mm)*16 + c;
                float yt = a[mm] + rb + ymixS[c*8 + mm];
                y_out[mc] = yt;
                float vv = X[(size_t)mc*256 + 255] + yt;
                out[mc*32 + step] = vv;
                if (step == 0) out[524288 + mc] = vv;
            }
        }
    }
}

// ---------------- host launch ----------------
extern "C" void kernel_launch(void* const* d_in, const int* in_sizes, int n_in,
                              void* d_out, int out_size)
{
    const float* X      = (const float*)d_in[0];
    const int*   phases = (const int*)  d_in[1];
    const float* gWih   = (const float*)d_in[2];
    const float* gWhh   = (const float*)d_in[3];
    const float* gbih   = (const float*)d_in[4];
    const float* gbhh   = (const float*)d_in[5];
    const float* lng    = (const float*)d_in[6];
    const float* lnb    = (const float*)d_in[7];
    const float* tW     = (const float*)d_in[8];
    const float* tb     = (const float*)d_in[9];
    const float* S      = (const float*)d_in[10];
    const float* G      = (const float*)d_in[11];
    const float* Wself  = (const float*)d_in[12];
    const float* Wneigh = (const float*)d_in[13];
    const float* cWih   = (const float*)d_in[14];
    const float* cWhh   = (const float*)d_in[15];
    const float* cbih   = (const float*)d_in[16];
    const float* cbhh   = (const float*)d_in[17];
    const float* readW  = (const float*)d_in[18];
    const float* readb  = (const float*)d_in[19];
    const float* Wk     = (const float*)d_in[20];
    const float* Wv     = (const float*)d_in[21];
    const float* ltau   = (const float*)d_in[22];
    float* out = (float*)d_out;

    const int k2_smem = K2_SMEM_BYTES;
    const int k3_smem = 2 * 128 * 168 * (int)sizeof(__half);  // 86016
    const int k5_smem = 2 * 128 * 136 * (int)sizeof(__half);  // 69632
    cudaFuncSetAttribute(k2_gru, cudaFuncAttributeMaxDynamicSharedMemorySize, k2_smem);
    cudaFuncSetAttribute(k3_hgemm, cudaFuncAttributeMaxDynamicSharedMemorySize, k3_smem);
    cudaFuncSetAttribute(k5_hgemm, cudaFuncAttributeMaxDynamicSharedMemorySize, k5_smem);

    k0_prep<<<1, 256>>>(Wneigh, Wself, Wk, Wv, S, G, tW, tb, ltau);
    {
        int total = 16*384*144 + 24*17*32;
        k_trans<<<(total + 255)/256, 256>>>(gWih, gWhh, cWih, cWhh);
    }
    k2_gru<<<128, 384, k2_smem>>>(X, gbih, gbhh, lng, lnb);
    k3_hgemm<<<dim3(2048, 2), 256, k3_smem>>>();
    k4_mix<<<dim3(32, 64), 256>>>(phases);
    k5_hgemm<<<dim3(2048, 2), 256, k5_smem>>>();
    k6_init<<<512, 256>>>();
    for (int s = 0; s < 32; s++) {
        d_s1<<<1024, 256>>>(phases, s);
        d_s2<<<128, 384>>>(X, cbih, cbhh, readW, readb, out, s);
    }
    (void)in_sizes; (void)n_in; (void)out_size;
}